// round 7
// baseline (speedup 1.0000x reference)
#include <cuda_runtime.h>
#include <cuda_bf16.h>
#include <cstdint>

// Problem constants
#define DIMC    192
#define QKV_N   576
#define NWIN    144
#define NHEADS  6
#define HD      32
#define TOW     64
#define BATCH   30
#define MTOT    (BATCH * TOW * NWIN)   // 276480 rows
#define ATT_SCALE 0.17677669529663687f

// Scratch
static __device__ float g_qkv[(size_t)MTOT * QKV_N];
static __device__ float g_att[(size_t)MTOT * DIMC];
static __device__ float g_biasg[(size_t)NHEADS * TOW * NWIN * NWIN];

// ---------------------------------------------------------------------------
// tf32 mma.sync helpers (tcgen05 unavailable: harness builds compute_103 PTX)
// ---------------------------------------------------------------------------
__device__ __forceinline__ uint32_t f32_to_tf32(float x) {
    uint32_t r;
    asm("cvt.rna.tf32.f32 %0, %1;" : "=r"(r) : "f"(x));
    return r;
}

__device__ __forceinline__ void mma_tf32_16x8x8(
    float& c0, float& c1, float& c2, float& c3,
    uint32_t a0, uint32_t a1, uint32_t a2, uint32_t a3,
    uint32_t b0, uint32_t b1)
{
    asm volatile(
        "mma.sync.aligned.m16n8k8.row.col.f32.tf32.tf32.f32 "
        "{%0,%1,%2,%3}, {%4,%5,%6,%7}, {%8,%9}, {%0,%1,%2,%3};"
        : "+f"(c0), "+f"(c1), "+f"(c2), "+f"(c3)
        : "r"(a0), "r"(a1), "r"(a2), "r"(a3), "r"(b0), "r"(b1));
}

// ---------------------------------------------------------------------------
// tf32 mma.sync GEMM, double-buffered smem (unchanged from R5/R6).
// ---------------------------------------------------------------------------
#define APITCH 36
#define AS_WORDS (128 * APITCH)
#define BS_WORDS (64 * APITCH)
#define GEMM_SMEM_B ((2 * AS_WORDS + 2 * BS_WORDS) * 4)

__global__ __launch_bounds__(256, 2)
void gemm_mma_kernel(const float* __restrict__ A, const float* __restrict__ B,
                     const float* __restrict__ bias, float* __restrict__ C,
                     int N, int K, int scaleCols, float scale)
{
    extern __shared__ uint32_t gsm[];
    uint32_t* AsBase = gsm;
    uint32_t* BsBase = gsm + 2 * AS_WORDS;

    const int tid  = threadIdx.x;
    const int warp = tid >> 5, lane = tid & 31;
    const int wm   = warp & 3, wn = warp >> 2;
    const int grp  = lane >> 2, tg = lane & 3;
    const int n0   = blockIdx.x * 64;
    const int m0   = blockIdx.y * 128;

    float c[2][4][4];
#pragma unroll
    for (int mt = 0; mt < 2; mt++)
#pragma unroll
        for (int nt = 0; nt < 4; nt++)
#pragma unroll
            for (int r = 0; r < 4; r++) c[mt][nt][r] = 0.f;

    const float* Ag = A + (size_t)m0 * K;
    const float* Bg = B + (size_t)n0 * K;

    const int arow = tid >> 3, acol = (tid & 7) * 4;
    const int brow = tid >> 3, bcol = (tid & 7) * 4;

    {
        float4 av[4], bv[2];
#pragma unroll
        for (int it = 0; it < 4; it++)
            av[it] = *(const float4*)&Ag[(size_t)(arow + it * 32) * K + acol];
#pragma unroll
        for (int it = 0; it < 2; it++)
            bv[it] = *(const float4*)&Bg[(size_t)(brow + it * 32) * K + bcol];
#pragma unroll
        for (int it = 0; it < 4; it++) {
            uint32_t* d = &AsBase[(arow + it * 32) * APITCH + acol];
            d[0] = f32_to_tf32(av[it].x); d[1] = f32_to_tf32(av[it].y);
            d[2] = f32_to_tf32(av[it].z); d[3] = f32_to_tf32(av[it].w);
        }
#pragma unroll
        for (int it = 0; it < 2; it++) {
            uint32_t* d = &BsBase[(brow + it * 32) * APITCH + bcol];
            d[0] = f32_to_tf32(bv[it].x); d[1] = f32_to_tf32(bv[it].y);
            d[2] = f32_to_tf32(bv[it].z); d[3] = f32_to_tf32(bv[it].w);
        }
    }
    __syncthreads();

    int buf = 0;
    for (int k0 = 0; k0 < K; k0 += 32) {
        const bool has_next = (k0 + 32 < K);
        float4 av[4], bv[2];
        if (has_next) {
#pragma unroll
            for (int it = 0; it < 4; it++)
                av[it] = *(const float4*)&Ag[(size_t)(arow + it * 32) * K + k0 + 32 + acol];
#pragma unroll
            for (int it = 0; it < 2; it++)
                bv[it] = *(const float4*)&Bg[(size_t)(brow + it * 32) * K + k0 + 32 + bcol];
        }

        const uint32_t* As = AsBase + buf * AS_WORDS;
        const uint32_t* Bs = BsBase + buf * BS_WORDS;
#pragma unroll
        for (int ks = 0; ks < 4; ks++) {
            const int k8 = ks * 8;
            uint32_t a[2][4];
#pragma unroll
            for (int mt = 0; mt < 2; mt++) {
                int rb = wm * 32 + mt * 16;
                a[mt][0] = As[(rb + grp) * APITCH + k8 + tg];
                a[mt][1] = As[(rb + grp + 8) * APITCH + k8 + tg];
                a[mt][2] = As[(rb + grp) * APITCH + k8 + tg + 4];
                a[mt][3] = As[(rb + grp + 8) * APITCH + k8 + tg + 4];
            }
#pragma unroll
            for (int nt = 0; nt < 4; nt++) {
                int nb = wn * 32 + nt * 8;
                uint32_t b0 = Bs[(nb + grp) * APITCH + k8 + tg];
                uint32_t b1 = Bs[(nb + grp) * APITCH + k8 + tg + 4];
#pragma unroll
                for (int mt = 0; mt < 2; mt++)
                    mma_tf32_16x8x8(c[mt][nt][0], c[mt][nt][1],
                                    c[mt][nt][2], c[mt][nt][3],
                                    a[mt][0], a[mt][1], a[mt][2], a[mt][3],
                                    b0, b1);
            }
        }

        if (has_next) {
            uint32_t* Asn = AsBase + (buf ^ 1) * AS_WORDS;
            uint32_t* Bsn = BsBase + (buf ^ 1) * BS_WORDS;
#pragma unroll
            for (int it = 0; it < 4; it++) {
                uint32_t* d = &Asn[(arow + it * 32) * APITCH + acol];
                d[0] = f32_to_tf32(av[it].x); d[1] = f32_to_tf32(av[it].y);
                d[2] = f32_to_tf32(av[it].z); d[3] = f32_to_tf32(av[it].w);
            }
#pragma unroll
            for (int it = 0; it < 2; it++) {
                uint32_t* d = &Bsn[(brow + it * 32) * APITCH + bcol];
                d[0] = f32_to_tf32(bv[it].x); d[1] = f32_to_tf32(bv[it].y);
                d[2] = f32_to_tf32(bv[it].z); d[3] = f32_to_tf32(bv[it].w);
            }
            __syncthreads();
        }
        buf ^= 1;
    }

#pragma unroll
    for (int mt = 0; mt < 2; mt++) {
#pragma unroll
        for (int nt = 0; nt < 4; nt++) {
            int col = n0 + wn * 32 + nt * 8 + tg * 2;
            float b0 = bias[col], b1 = bias[col + 1];
            float s0 = (col     < scaleCols) ? scale : 1.f;
            float s1 = (col + 1 < scaleCols) ? scale : 1.f;
            int r0 = m0 + wm * 32 + mt * 16 + grp;
            float2 v0 = make_float2((c[mt][nt][0] + b0) * s0,
                                    (c[mt][nt][1] + b1) * s1);
            float2 v1 = make_float2((c[mt][nt][2] + b0) * s0,
                                    (c[mt][nt][3] + b1) * s1);
            *(float2*)&C[(size_t)r0 * N + col]       = v0;
            *(float2*)&C[(size_t)(r0 + 8) * N + col] = v1;
        }
    }
}

// ---------------------------------------------------------------------------
// Bias pre-gather
// ---------------------------------------------------------------------------
__global__ void bias_gather_kernel(const float* __restrict__ table,
                                   const int* __restrict__ pos)
{
    const int w = blockIdx.x, h = blockIdx.y;
    float* dst = g_biasg + (size_t)(h * TOW + w) * (NWIN * NWIN);
    for (int idx = threadIdx.x; idx < NWIN * NWIN; idx += blockDim.x) {
        int p = pos[idx];
        dst[idx] = table[((size_t)p * TOW + w) * NHEADS + h];
    }
}

// ---------------------------------------------------------------------------
// Tensor-core attention v5: one CTA per (b,w,h,seg), seg = 48 query rows,
// 96 threads = 3 warps. K and V staged in smem via COALESCED float4 LDG;
// fragments fed by conflict-free scalar LDS (pitch 36 for K, 40 for V).
// Bias preloaded coalesced into S and accumulated in the QK^T epilogue.
// smem: Kt[144*36] + Vs[144*40] + S[48*148] = 72192 B -> 3 CTAs/SM.
// ---------------------------------------------------------------------------
#define ATTN_THREADS 96
#define SEG_ROWS 48
#define NSEG 3
#define KP  36
#define VP  40
#define SP  148
#define KT_OFF 0
#define VS_OFF (NWIN * KP)
#define SS_OFF (VS_OFF + NWIN * VP)
#define ATTN_SMEM_B ((SS_OFF + SEG_ROWS * SP) * 4)

__global__ __launch_bounds__(ATTN_THREADS)
void attn_mma_kernel()
{
    extern __shared__ uint32_t smw[];
    uint32_t* Kt = smw + KT_OFF;
    uint32_t* Vs = smw + VS_OFF;
    float*    S  = (float*)(smw + SS_OFF);
    uint32_t* Su = smw + SS_OFF;

    const int w = blockIdx.x, b = blockIdx.y;
    const int h = blockIdx.z / NSEG, seg = blockIdx.z % NSEG;
    const int tid  = threadIdx.x;
    const int warp = tid >> 5, lane = tid & 31;
    const int grp  = lane >> 2, tg = lane & 3;
    const int lrb  = warp * 16;              // local row base in S
    const int rb   = seg * SEG_ROWS + lrb;   // global query row base

    const size_t base = (size_t)(b * TOW + w) * NWIN * QKV_N + h * HD;
    const float* __restrict__ Qg = g_qkv + base;
    const float* __restrict__ Kg = Qg + 192;
    const float* __restrict__ Vg = Qg + 384;

    // --- stage K and V into smem (coalesced float4) ---
    for (int idx = tid; idx < NWIN * 8; idx += ATTN_THREADS) {
        const int i = idx >> 3, e0 = (idx & 7) * 4;
        float4 kk = *(const float4*)&Kg[(size_t)i * QKV_N + e0];
        float4 vv = *(const float4*)&Vg[(size_t)i * QKV_N + e0];
        uint32_t* kd = &Kt[i * KP + e0];
        kd[0] = f32_to_tf32(kk.x); kd[1] = f32_to_tf32(kk.y);
        kd[2] = f32_to_tf32(kk.z); kd[3] = f32_to_tf32(kk.w);
        uint32_t* vd = &Vs[i * VP + e0];
        vd[0] = f32_to_tf32(vv.x); vd[1] = f32_to_tf32(vv.y);
        vd[2] = f32_to_tf32(vv.z); vd[3] = f32_to_tf32(vv.w);
    }
    // --- preload bias into S (coalesced float4) ---
    const float* bptr = g_biasg + (size_t)(h * TOW + w) * (NWIN * NWIN)
                        + (size_t)seg * SEG_ROWS * NWIN;
    for (int idx = tid; idx < SEG_ROWS * 36; idx += ATTN_THREADS) {
        const int r = idx / 36, j = (idx % 36) * 4;
        *(float4*)&S[r * SP + j] = *(const float4*)&bptr[r * NWIN + j];
    }

    // Q A-fragments for this warp's 16 rows (global; reused across 18 n-tiles)
    uint32_t aq[4][4];
#pragma unroll
    for (int kt = 0; kt < 4; kt++) {
        const int k8 = kt * 8;
        aq[kt][0] = f32_to_tf32(Qg[(size_t)(rb + grp) * QKV_N + k8 + tg]);
        aq[kt][1] = f32_to_tf32(Qg[(size_t)(rb + grp + 8) * QKV_N + k8 + tg]);
        aq[kt][2] = f32_to_tf32(Qg[(size_t)(rb + grp) * QKV_N + k8 + tg + 4]);
        aq[kt][3] = f32_to_tf32(Qg[(size_t)(rb + grp + 8) * QKV_N + k8 + tg + 4]);
    }
    __syncthreads();

    // --- S = Q K^T + bias ---
#pragma unroll 3
    for (int nt = 0; nt < 18; nt++) {
        const int nb = nt * 8;
        float c0 = 0.f, c1 = 0.f, c2 = 0.f, c3 = 0.f;
#pragma unroll
        for (int kt = 0; kt < 4; kt++) {
            const int k8 = kt * 8;
            uint32_t b0 = Kt[(nb + grp) * KP + k8 + tg];
            uint32_t b1 = Kt[(nb + grp) * KP + k8 + tg + 4];
            mma_tf32_16x8x8(c0, c1, c2, c3,
                            aq[kt][0], aq[kt][1], aq[kt][2], aq[kt][3], b0, b1);
        }
        const int col = nb + tg * 2;
        float2 s0 = *(float2*)&S[(lrb + grp) * SP + col];
        float2 s1 = *(float2*)&S[(lrb + grp + 8) * SP + col];
        *(float2*)&S[(lrb + grp) * SP + col]     = make_float2(c0 + s0.x, c1 + s0.y);
        *(float2*)&S[(lrb + grp + 8) * SP + col] = make_float2(c2 + s1.x, c3 + s1.y);
    }
    __syncthreads();

    // --- softmax per row; write tf32 probabilities in-place ---
    for (int r = 0; r < 16; r++) {
        float* row = &S[(lrb + r) * SP];
        float mx = -1e30f;
        for (int j = lane; j < NWIN; j += 32) mx = fmaxf(mx, row[j]);
#pragma unroll
        for (int o = 16; o; o >>= 1) mx = fmaxf(mx, __shfl_xor_sync(0xffffffffu, mx, o));
        float pv[5];
        float sum = 0.f;
        int cnt = 0;
        for (int j = lane; j < NWIN; j += 32) {
            float p = __expf(row[j] - mx);
            pv[cnt++] = p;
            sum += p;
        }
#pragma unroll
        for (int o = 16; o; o >>= 1) sum += __shfl_xor_sync(0xffffffffu, sum, o);
        float inv = 1.f / sum;
        cnt = 0;
        uint32_t* rowu = &Su[(lrb + r) * SP];
        for (int j = lane; j < NWIN; j += 32) rowu[j] = f32_to_tf32(pv[cnt++] * inv);
    }
    __syncthreads();

    // --- O = P V ---
    float c[4][4];
#pragma unroll
    for (int nt = 0; nt < 4; nt++)
#pragma unroll
        for (int r = 0; r < 4; r++) c[nt][r] = 0.f;

#pragma unroll 3
    for (int kk = 0; kk < 18; kk++) {
        const int k8 = kk * 8;
        uint32_t a0 = Su[(lrb + grp) * SP + k8 + tg];
        uint32_t a1 = Su[(lrb + grp + 8) * SP + k8 + tg];
        uint32_t a2 = Su[(lrb + grp) * SP + k8 + tg + 4];
        uint32_t a3 = Su[(lrb + grp + 8) * SP + k8 + tg + 4];
#pragma unroll
        for (int nt = 0; nt < 4; nt++) {
            uint32_t b0 = Vs[(k8 + tg) * VP + nt * 8 + grp];
            uint32_t b1 = Vs[(k8 + tg + 4) * VP + nt * 8 + grp];
            mma_tf32_16x8x8(c[nt][0], c[nt][1], c[nt][2], c[nt][3],
                            a0, a1, a2, a3, b0, b1);
        }
    }

    const size_t obase = (size_t)(b * TOW + w) * NWIN * DIMC + h * HD;
#pragma unroll
    for (int nt = 0; nt < 4; nt++) {
        const int col = nt * 8 + tg * 2;
        *(float2*)&g_att[obase + (size_t)(rb + grp) * DIMC + col] =
            make_float2(c[nt][0], c[nt][1]);
        *(float2*)&g_att[obase + (size_t)(rb + grp + 8) * DIMC + col] =
            make_float2(c[nt][2], c[nt][3]);
    }
}

// ---------------------------------------------------------------------------
extern "C" void kernel_launch(void* const* d_in, const int* in_sizes, int n_in,
                              void* d_out, int out_size)
{
    const float* x      = (const float*)d_in[0];
    const float* qkv_w  = (const float*)d_in[1];
    const float* qkv_b  = (const float*)d_in[2];
    const float* proj_w = (const float*)d_in[3];
    const float* proj_b = (const float*)d_in[4];
    const float* table  = (const float*)d_in[5];
    const int*   pos    = (const int*)d_in[6];
    float* out = (float*)d_out;

    float *qkv_s, *att_s;
    cudaGetSymbolAddress((void**)&qkv_s, g_qkv);
    cudaGetSymbolAddress((void**)&att_s, g_att);

    cudaFuncSetAttribute(gemm_mma_kernel, cudaFuncAttributeMaxDynamicSharedMemorySize,
                         GEMM_SMEM_B);
    cudaFuncSetAttribute(attn_mma_kernel, cudaFuncAttributeMaxDynamicSharedMemorySize,
                         ATTN_SMEM_B);

    // 1) fused QKV projection (mma.sync tf32; +bias, q scaled)
    {
        dim3 grid(QKV_N / 64, MTOT / 128);
        gemm_mma_kernel<<<grid, 256, GEMM_SMEM_B>>>(x, qkv_w, qkv_b, qkv_s,
                                                    QKV_N, DIMC, DIMC, ATT_SCALE);
    }
    // 2) bias pre-gather
    {
        dim3 grid(TOW, NHEADS);
        bias_gather_kernel<<<grid, 256>>>(table, pos);
    }
    // 3) windowed attention (smem-staged K/V, coalesced loads)
    {
        dim3 grid(TOW, BATCH, NHEADS * NSEG);
        attn_mma_kernel<<<grid, ATTN_THREADS, ATTN_SMEM_B>>>();
    }
    // 4) output projection (mma.sync tf32)
    {
        dim3 grid(DIMC / 64, MTOT / 128);
        gemm_mma_kernel<<<grid, 256, GEMM_SMEM_B>>>(att_s, proj_w, proj_b, out,
                                                    DIMC, DIMC, 0, 1.0f);
    }
}

// round 8
// speedup vs baseline: 1.4680x; 1.4680x over previous
#include <cuda_runtime.h>
#include <cuda_bf16.h>
#include <cstdint>

// Problem constants
#define DIMC    192
#define QKV_N   576
#define NWIN    144
#define NHEADS  6
#define HD      32
#define TOW     64
#define BATCH   30
#define MTOT    (BATCH * TOW * NWIN)   // 276480 rows
#define ATT_SCALE 0.17677669529663687f

// Scratch
static __device__ float g_qkv[(size_t)MTOT * QKV_N];
static __device__ float g_att[(size_t)MTOT * DIMC];
static __device__ float g_biasg[(size_t)NHEADS * TOW * NWIN * NWIN];

// ---------------------------------------------------------------------------
// tf32 mma.sync helpers (tcgen05 unavailable: harness builds compute_103 PTX)
// ---------------------------------------------------------------------------
__device__ __forceinline__ uint32_t f32_to_tf32(float x) {
    uint32_t r;
    asm("cvt.rna.tf32.f32 %0, %1;" : "=r"(r) : "f"(x));
    return r;
}

__device__ __forceinline__ void mma_tf32_16x8x8(
    float& c0, float& c1, float& c2, float& c3,
    uint32_t a0, uint32_t a1, uint32_t a2, uint32_t a3,
    uint32_t b0, uint32_t b1)
{
    asm volatile(
        "mma.sync.aligned.m16n8k8.row.col.f32.tf32.tf32.f32 "
        "{%0,%1,%2,%3}, {%4,%5,%6,%7}, {%8,%9}, {%0,%1,%2,%3};"
        : "+f"(c0), "+f"(c1), "+f"(c2), "+f"(c3)
        : "r"(a0), "r"(a1), "r"(a2), "r"(a3), "r"(b0), "r"(b1));
}

// ---------------------------------------------------------------------------
// tf32 mma.sync GEMM, double-buffered smem (unchanged from R6).
// ---------------------------------------------------------------------------
#define APITCH 36
#define AS_WORDS (128 * APITCH)
#define BS_WORDS (64 * APITCH)
#define GEMM_SMEM_B ((2 * AS_WORDS + 2 * BS_WORDS) * 4)

__global__ __launch_bounds__(256, 2)
void gemm_mma_kernel(const float* __restrict__ A, const float* __restrict__ B,
                     const float* __restrict__ bias, float* __restrict__ C,
                     int N, int K, int scaleCols, float scale)
{
    extern __shared__ uint32_t gsm[];
    uint32_t* AsBase = gsm;
    uint32_t* BsBase = gsm + 2 * AS_WORDS;

    const int tid  = threadIdx.x;
    const int warp = tid >> 5, lane = tid & 31;
    const int wm   = warp & 3, wn = warp >> 2;
    const int grp  = lane >> 2, tg = lane & 3;
    const int n0   = blockIdx.x * 64;
    const int m0   = blockIdx.y * 128;

    float c[2][4][4];
#pragma unroll
    for (int mt = 0; mt < 2; mt++)
#pragma unroll
        for (int nt = 0; nt < 4; nt++)
#pragma unroll
            for (int r = 0; r < 4; r++) c[mt][nt][r] = 0.f;

    const float* Ag = A + (size_t)m0 * K;
    const float* Bg = B + (size_t)n0 * K;

    const int arow = tid >> 3, acol = (tid & 7) * 4;
    const int brow = tid >> 3, bcol = (tid & 7) * 4;

    {
        float4 av[4], bv[2];
#pragma unroll
        for (int it = 0; it < 4; it++)
            av[it] = *(const float4*)&Ag[(size_t)(arow + it * 32) * K + acol];
#pragma unroll
        for (int it = 0; it < 2; it++)
            bv[it] = *(const float4*)&Bg[(size_t)(brow + it * 32) * K + bcol];
#pragma unroll
        for (int it = 0; it < 4; it++) {
            uint32_t* d = &AsBase[(arow + it * 32) * APITCH + acol];
            d[0] = f32_to_tf32(av[it].x); d[1] = f32_to_tf32(av[it].y);
            d[2] = f32_to_tf32(av[it].z); d[3] = f32_to_tf32(av[it].w);
        }
#pragma unroll
        for (int it = 0; it < 2; it++) {
            uint32_t* d = &BsBase[(brow + it * 32) * APITCH + bcol];
            d[0] = f32_to_tf32(bv[it].x); d[1] = f32_to_tf32(bv[it].y);
            d[2] = f32_to_tf32(bv[it].z); d[3] = f32_to_tf32(bv[it].w);
        }
    }
    __syncthreads();

    int buf = 0;
    for (int k0 = 0; k0 < K; k0 += 32) {
        const bool has_next = (k0 + 32 < K);
        float4 av[4], bv[2];
        if (has_next) {
#pragma unroll
            for (int it = 0; it < 4; it++)
                av[it] = *(const float4*)&Ag[(size_t)(arow + it * 32) * K + k0 + 32 + acol];
#pragma unroll
            for (int it = 0; it < 2; it++)
                bv[it] = *(const float4*)&Bg[(size_t)(brow + it * 32) * K + k0 + 32 + bcol];
        }

        const uint32_t* As = AsBase + buf * AS_WORDS;
        const uint32_t* Bs = BsBase + buf * BS_WORDS;
#pragma unroll
        for (int ks = 0; ks < 4; ks++) {
            const int k8 = ks * 8;
            uint32_t a[2][4];
#pragma unroll
            for (int mt = 0; mt < 2; mt++) {
                int rb = wm * 32 + mt * 16;
                a[mt][0] = As[(rb + grp) * APITCH + k8 + tg];
                a[mt][1] = As[(rb + grp + 8) * APITCH + k8 + tg];
                a[mt][2] = As[(rb + grp) * APITCH + k8 + tg + 4];
                a[mt][3] = As[(rb + grp + 8) * APITCH + k8 + tg + 4];
            }
#pragma unroll
            for (int nt = 0; nt < 4; nt++) {
                int nb = wn * 32 + nt * 8;
                uint32_t b0 = Bs[(nb + grp) * APITCH + k8 + tg];
                uint32_t b1 = Bs[(nb + grp) * APITCH + k8 + tg + 4];
#pragma unroll
                for (int mt = 0; mt < 2; mt++)
                    mma_tf32_16x8x8(c[mt][nt][0], c[mt][nt][1],
                                    c[mt][nt][2], c[mt][nt][3],
                                    a[mt][0], a[mt][1], a[mt][2], a[mt][3],
                                    b0, b1);
            }
        }

        if (has_next) {
            uint32_t* Asn = AsBase + (buf ^ 1) * AS_WORDS;
            uint32_t* Bsn = BsBase + (buf ^ 1) * BS_WORDS;
#pragma unroll
            for (int it = 0; it < 4; it++) {
                uint32_t* d = &Asn[(arow + it * 32) * APITCH + acol];
                d[0] = f32_to_tf32(av[it].x); d[1] = f32_to_tf32(av[it].y);
                d[2] = f32_to_tf32(av[it].z); d[3] = f32_to_tf32(av[it].w);
            }
#pragma unroll
            for (int it = 0; it < 2; it++) {
                uint32_t* d = &Bsn[(brow + it * 32) * APITCH + bcol];
                d[0] = f32_to_tf32(bv[it].x); d[1] = f32_to_tf32(bv[it].y);
                d[2] = f32_to_tf32(bv[it].z); d[3] = f32_to_tf32(bv[it].w);
            }
            __syncthreads();
        }
        buf ^= 1;
    }

#pragma unroll
    for (int mt = 0; mt < 2; mt++) {
#pragma unroll
        for (int nt = 0; nt < 4; nt++) {
            int col = n0 + wn * 32 + nt * 8 + tg * 2;
            float b0 = bias[col], b1 = bias[col + 1];
            float s0 = (col     < scaleCols) ? scale : 1.f;
            float s1 = (col + 1 < scaleCols) ? scale : 1.f;
            int r0 = m0 + wm * 32 + mt * 16 + grp;
            float2 v0 = make_float2((c[mt][nt][0] + b0) * s0,
                                    (c[mt][nt][1] + b1) * s1);
            float2 v1 = make_float2((c[mt][nt][2] + b0) * s0,
                                    (c[mt][nt][3] + b1) * s1);
            *(float2*)&C[(size_t)r0 * N + col]       = v0;
            *(float2*)&C[(size_t)(r0 + 8) * N + col] = v1;
        }
    }
}

// ---------------------------------------------------------------------------
// Bias pre-gather
// ---------------------------------------------------------------------------
__global__ void bias_gather_kernel(const float* __restrict__ table,
                                   const int* __restrict__ pos)
{
    const int w = blockIdx.x, h = blockIdx.y;
    float* dst = g_biasg + (size_t)(h * TOW + w) * (NWIN * NWIN);
    for (int idx = threadIdx.x; idx < NWIN * NWIN; idx += blockDim.x) {
        int p = pos[idx];
        dst[idx] = table[((size_t)p * TOW + w) * NHEADS + h];
    }
}

// ---------------------------------------------------------------------------
// Tensor-core attention v6: one CTA per (b,w,h,seg), seg = 48 query rows,
// 96 threads = 3 warps. K staged in a smem buffer (pitch 36) for QK^T;
// after the phase barrier the SAME buffer is re-staged with V (pitch 40)
// during softmax. smem = KV 23KB + S 28.4KB = 51.5KB -> 4 CTAs/SM (12 warps).
// All LDS access patterns bank-conflict-free; staging LDGs are float4 coalesced.
// ---------------------------------------------------------------------------
#define ATTN_THREADS 96
#define SEG_ROWS 48
#define NSEG 3
#define KP  36
#define VP  40
#define SP  148
#define KV_OFF 0
#define KV_WORDS (NWIN * VP)          // 5760 words, holds K(pitch36) or V(pitch40)
#define SS_OFF KV_WORDS
#define ATTN_SMEM_B ((SS_OFF + SEG_ROWS * SP) * 4)   // 51456 B

__global__ __launch_bounds__(ATTN_THREADS)
void attn_mma_kernel()
{
    extern __shared__ uint32_t smw[];
    uint32_t* KV = smw + KV_OFF;
    float*    S  = (float*)(smw + SS_OFF);
    uint32_t* Su = smw + SS_OFF;

    const int w = blockIdx.x, b = blockIdx.y;
    const int h = blockIdx.z / NSEG, seg = blockIdx.z % NSEG;
    const int tid  = threadIdx.x;
    const int warp = tid >> 5, lane = tid & 31;
    const int grp  = lane >> 2, tg = lane & 3;
    const int lrb  = warp * 16;              // local row base in S
    const int rb   = seg * SEG_ROWS + lrb;   // global query row base

    const size_t base = (size_t)(b * TOW + w) * NWIN * QKV_N + h * HD;
    const float* __restrict__ Qg = g_qkv + base;
    const float* __restrict__ Kg = Qg + 192;
    const float* __restrict__ Vg = Qg + 384;

    // --- phase 1: stage K (pitch 36, coalesced float4), preload bias into S,
    //              load Q fragments from global ---
    for (int idx = tid; idx < NWIN * 8; idx += ATTN_THREADS) {
        const int i = idx >> 3, e0 = (idx & 7) * 4;
        float4 kk = *(const float4*)&Kg[(size_t)i * QKV_N + e0];
        uint32_t* kd = &KV[i * KP + e0];
        kd[0] = f32_to_tf32(kk.x); kd[1] = f32_to_tf32(kk.y);
        kd[2] = f32_to_tf32(kk.z); kd[3] = f32_to_tf32(kk.w);
    }
    const float* bptr = g_biasg + (size_t)(h * TOW + w) * (NWIN * NWIN)
                        + (size_t)seg * SEG_ROWS * NWIN;
    for (int idx = tid; idx < SEG_ROWS * 36; idx += ATTN_THREADS) {
        const int r = idx / 36, j = (idx % 36) * 4;
        *(float4*)&S[r * SP + j] = *(const float4*)&bptr[r * NWIN + j];
    }

    uint32_t aq[4][4];
#pragma unroll
    for (int kt = 0; kt < 4; kt++) {
        const int k8 = kt * 8;
        aq[kt][0] = f32_to_tf32(Qg[(size_t)(rb + grp) * QKV_N + k8 + tg]);
        aq[kt][1] = f32_to_tf32(Qg[(size_t)(rb + grp + 8) * QKV_N + k8 + tg]);
        aq[kt][2] = f32_to_tf32(Qg[(size_t)(rb + grp) * QKV_N + k8 + tg + 4]);
        aq[kt][3] = f32_to_tf32(Qg[(size_t)(rb + grp + 8) * QKV_N + k8 + tg + 4]);
    }
    __syncthreads();

    // --- phase 2: S = Q K^T + bias ---
#pragma unroll 3
    for (int nt = 0; nt < 18; nt++) {
        const int nb = nt * 8;
        float c0 = 0.f, c1 = 0.f, c2 = 0.f, c3 = 0.f;
#pragma unroll
        for (int kt = 0; kt < 4; kt++) {
            const int k8 = kt * 8;
            uint32_t b0 = KV[(nb + grp) * KP + k8 + tg];
            uint32_t b1 = KV[(nb + grp) * KP + k8 + tg + 4];
            mma_tf32_16x8x8(c0, c1, c2, c3,
                            aq[kt][0], aq[kt][1], aq[kt][2], aq[kt][3], b0, b1);
        }
        const int col = nb + tg * 2;
        float2 s0 = *(float2*)&S[(lrb + grp) * SP + col];
        float2 s1 = *(float2*)&S[(lrb + grp + 8) * SP + col];
        *(float2*)&S[(lrb + grp) * SP + col]     = make_float2(c0 + s0.x, c1 + s0.y);
        *(float2*)&S[(lrb + grp + 8) * SP + col] = make_float2(c2 + s1.x, c3 + s1.y);
    }
    __syncthreads();   // K consumed; KV buffer free for V

    // --- phase 3: stage V (pitch 40) + softmax (independent work, overlaps) ---
    for (int idx = tid; idx < NWIN * 8; idx += ATTN_THREADS) {
        const int i = idx >> 3, e0 = (idx & 7) * 4;
        float4 vv = *(const float4*)&Vg[(size_t)i * QKV_N + e0];
        uint32_t* vd = &KV[i * VP + e0];
        vd[0] = f32_to_tf32(vv.x); vd[1] = f32_to_tf32(vv.y);
        vd[2] = f32_to_tf32(vv.z); vd[3] = f32_to_tf32(vv.w);
    }
    for (int r = 0; r < 16; r++) {
        float* row = &S[(lrb + r) * SP];
        float mx = -1e30f;
        for (int j = lane; j < NWIN; j += 32) mx = fmaxf(mx, row[j]);
#pragma unroll
        for (int o = 16; o; o >>= 1) mx = fmaxf(mx, __shfl_xor_sync(0xffffffffu, mx, o));
        float pv[5];
        float sum = 0.f;
        int cnt = 0;
        for (int j = lane; j < NWIN; j += 32) {
            float p = __expf(row[j] - mx);
            pv[cnt++] = p;
            sum += p;
        }
#pragma unroll
        for (int o = 16; o; o >>= 1) sum += __shfl_xor_sync(0xffffffffu, sum, o);
        float inv = 1.f / sum;
        cnt = 0;
        uint32_t* rowu = &Su[(lrb + r) * SP];
        for (int j = lane; j < NWIN; j += 32) rowu[j] = f32_to_tf32(pv[cnt++] * inv);
    }
    __syncthreads();

    // --- phase 4: O = P V ---
    float c[4][4];
#pragma unroll
    for (int nt = 0; nt < 4; nt++)
#pragma unroll
        for (int r = 0; r < 4; r++) c[nt][r] = 0.f;

#pragma unroll 3
    for (int kk = 0; kk < 18; kk++) {
        const int k8 = kk * 8;
        uint32_t a0 = Su[(lrb + grp) * SP + k8 + tg];
        uint32_t a1 = Su[(lrb + grp + 8) * SP + k8 + tg];
        uint32_t a2 = Su[(lrb + grp) * SP + k8 + tg + 4];
        uint32_t a3 = Su[(lrb + grp + 8) * SP + k8 + tg + 4];
#pragma unroll
        for (int nt = 0; nt < 4; nt++) {
            uint32_t b0 = KV[(k8 + tg) * VP + nt * 8 + grp];
            uint32_t b1 = KV[(k8 + tg + 4) * VP + nt * 8 + grp];
            mma_tf32_16x8x8(c[nt][0], c[nt][1], c[nt][2], c[nt][3],
                            a0, a1, a2, a3, b0, b1);
        }
    }

    const size_t obase = (size_t)(b * TOW + w) * NWIN * DIMC + h * HD;
#pragma unroll
    for (int nt = 0; nt < 4; nt++) {
        const int col = nt * 8 + tg * 2;
        *(float2*)&g_att[obase + (size_t)(rb + grp) * DIMC + col] =
            make_float2(c[nt][0], c[nt][1]);
        *(float2*)&g_att[obase + (size_t)(rb + grp + 8) * DIMC + col] =
            make_float2(c[nt][2], c[nt][3]);
    }
}

// ---------------------------------------------------------------------------
extern "C" void kernel_launch(void* const* d_in, const int* in_sizes, int n_in,
                              void* d_out, int out_size)
{
    const float* x      = (const float*)d_in[0];
    const float* qkv_w  = (const float*)d_in[1];
    const float* qkv_b  = (const float*)d_in[2];
    const float* proj_w = (const float*)d_in[3];
    const float* proj_b = (const float*)d_in[4];
    const float* table  = (const float*)d_in[5];
    const int*   pos    = (const int*)d_in[6];
    float* out = (float*)d_out;

    float *qkv_s, *att_s;
    cudaGetSymbolAddress((void**)&qkv_s, g_qkv);
    cudaGetSymbolAddress((void**)&att_s, g_att);

    cudaFuncSetAttribute(gemm_mma_kernel, cudaFuncAttributeMaxDynamicSharedMemorySize,
                         GEMM_SMEM_B);
    cudaFuncSetAttribute(attn_mma_kernel, cudaFuncAttributeMaxDynamicSharedMemorySize,
                         ATTN_SMEM_B);

    // 1) fused QKV projection (mma.sync tf32; +bias, q scaled)
    {
        dim3 grid(QKV_N / 64, MTOT / 128);
        gemm_mma_kernel<<<grid, 256, GEMM_SMEM_B>>>(x, qkv_w, qkv_b, qkv_s,
                                                    QKV_N, DIMC, DIMC, ATT_SCALE);
    }
    // 2) bias pre-gather
    {
        dim3 grid(TOW, NHEADS);
        bias_gather_kernel<<<grid, 256>>>(table, pos);
    }
    // 3) windowed attention (staged K->V buffer reuse, 4 CTAs/SM)
    {
        dim3 grid(TOW, BATCH, NHEADS * NSEG);
        attn_mma_kernel<<<grid, ATTN_THREADS, ATTN_SMEM_B>>>();
    }
    // 4) output projection (mma.sync tf32)
    {
        dim3 grid(DIMC / 64, MTOT / 128);
        gemm_mma_kernel<<<grid, 256, GEMM_SMEM_B>>>(att_s, proj_w, proj_b, out,
                                                    DIMC, DIMC, 0, 1.0f);
    }
}

// round 9
// speedup vs baseline: 2.1835x; 1.4875x over previous
#include <cuda_runtime.h>
#include <cuda_bf16.h>
#include <cstdint>

// Problem constants
#define DIMC    192
#define QKV_N   576
#define NWIN    144
#define NHEADS  6
#define HD      32
#define TOW     64
#define BATCH   30
#define MTOT    (BATCH * TOW * NWIN)   // 276480 rows
#define ATT_SCALE 0.17677669529663687f

// Scratch
static __device__ float g_qkv[(size_t)MTOT * QKV_N];
static __device__ float g_att[(size_t)MTOT * DIMC];
static __device__ float g_biasg[(size_t)NHEADS * TOW * NWIN * NWIN];

// ---------------------------------------------------------------------------
// tf32 mma.sync helpers
// ---------------------------------------------------------------------------
__device__ __forceinline__ uint32_t f32_to_tf32(float x) {
    uint32_t r;
    asm("cvt.rna.tf32.f32 %0, %1;" : "=r"(r) : "f"(x));
    return r;
}

__device__ __forceinline__ void mma_tf32_16x8x8(
    float& c0, float& c1, float& c2, float& c3,
    uint32_t a0, uint32_t a1, uint32_t a2, uint32_t a3,
    uint32_t b0, uint32_t b1)
{
    asm volatile(
        "mma.sync.aligned.m16n8k8.row.col.f32.tf32.tf32.f32 "
        "{%0,%1,%2,%3}, {%4,%5,%6,%7}, {%8,%9}, {%0,%1,%2,%3};"
        : "+f"(c0), "+f"(c1), "+f"(c2), "+f"(c3)
        : "r"(a0), "r"(a1), "r"(a2), "r"(a3), "r"(b0), "r"(b1));
}

// ---------------------------------------------------------------------------
// tf32 mma.sync GEMM, double-buffered smem (unchanged from R6/R8).
// ---------------------------------------------------------------------------
#define APITCH 36
#define AS_WORDS (128 * APITCH)
#define BS_WORDS (64 * APITCH)
#define GEMM_SMEM_B ((2 * AS_WORDS + 2 * BS_WORDS) * 4)

__global__ __launch_bounds__(256, 2)
void gemm_mma_kernel(const float* __restrict__ A, const float* __restrict__ B,
                     const float* __restrict__ bias, float* __restrict__ C,
                     int N, int K, int scaleCols, float scale)
{
    extern __shared__ uint32_t gsm[];
    uint32_t* AsBase = gsm;
    uint32_t* BsBase = gsm + 2 * AS_WORDS;

    const int tid  = threadIdx.x;
    const int warp = tid >> 5, lane = tid & 31;
    const int wm   = warp & 3, wn = warp >> 2;
    const int grp  = lane >> 2, tg = lane & 3;
    const int n0   = blockIdx.x * 64;
    const int m0   = blockIdx.y * 128;

    float c[2][4][4];
#pragma unroll
    for (int mt = 0; mt < 2; mt++)
#pragma unroll
        for (int nt = 0; nt < 4; nt++)
#pragma unroll
            for (int r = 0; r < 4; r++) c[mt][nt][r] = 0.f;

    const float* Ag = A + (size_t)m0 * K;
    const float* Bg = B + (size_t)n0 * K;

    const int arow = tid >> 3, acol = (tid & 7) * 4;
    const int brow = tid >> 3, bcol = (tid & 7) * 4;

    {
        float4 av[4], bv[2];
#pragma unroll
        for (int it = 0; it < 4; it++)
            av[it] = *(const float4*)&Ag[(size_t)(arow + it * 32) * K + acol];
#pragma unroll
        for (int it = 0; it < 2; it++)
            bv[it] = *(const float4*)&Bg[(size_t)(brow + it * 32) * K + bcol];
#pragma unroll
        for (int it = 0; it < 4; it++) {
            uint32_t* d = &AsBase[(arow + it * 32) * APITCH + acol];
            d[0] = f32_to_tf32(av[it].x); d[1] = f32_to_tf32(av[it].y);
            d[2] = f32_to_tf32(av[it].z); d[3] = f32_to_tf32(av[it].w);
        }
#pragma unroll
        for (int it = 0; it < 2; it++) {
            uint32_t* d = &BsBase[(brow + it * 32) * APITCH + bcol];
            d[0] = f32_to_tf32(bv[it].x); d[1] = f32_to_tf32(bv[it].y);
            d[2] = f32_to_tf32(bv[it].z); d[3] = f32_to_tf32(bv[it].w);
        }
    }
    __syncthreads();

    int buf = 0;
    for (int k0 = 0; k0 < K; k0 += 32) {
        const bool has_next = (k0 + 32 < K);
        float4 av[4], bv[2];
        if (has_next) {
#pragma unroll
            for (int it = 0; it < 4; it++)
                av[it] = *(const float4*)&Ag[(size_t)(arow + it * 32) * K + k0 + 32 + acol];
#pragma unroll
            for (int it = 0; it < 2; it++)
                bv[it] = *(const float4*)&Bg[(size_t)(brow + it * 32) * K + k0 + 32 + bcol];
        }

        const uint32_t* As = AsBase + buf * AS_WORDS;
        const uint32_t* Bs = BsBase + buf * BS_WORDS;
#pragma unroll
        for (int ks = 0; ks < 4; ks++) {
            const int k8 = ks * 8;
            uint32_t a[2][4];
#pragma unroll
            for (int mt = 0; mt < 2; mt++) {
                int rb = wm * 32 + mt * 16;
                a[mt][0] = As[(rb + grp) * APITCH + k8 + tg];
                a[mt][1] = As[(rb + grp + 8) * APITCH + k8 + tg];
                a[mt][2] = As[(rb + grp) * APITCH + k8 + tg + 4];
                a[mt][3] = As[(rb + grp + 8) * APITCH + k8 + tg + 4];
            }
#pragma unroll
            for (int nt = 0; nt < 4; nt++) {
                int nb = wn * 32 + nt * 8;
                uint32_t b0 = Bs[(nb + grp) * APITCH + k8 + tg];
                uint32_t b1 = Bs[(nb + grp) * APITCH + k8 + tg + 4];
#pragma unroll
                for (int mt = 0; mt < 2; mt++)
                    mma_tf32_16x8x8(c[mt][nt][0], c[mt][nt][1],
                                    c[mt][nt][2], c[mt][nt][3],
                                    a[mt][0], a[mt][1], a[mt][2], a[mt][3],
                                    b0, b1);
            }
        }

        if (has_next) {
            uint32_t* Asn = AsBase + (buf ^ 1) * AS_WORDS;
            uint32_t* Bsn = BsBase + (buf ^ 1) * BS_WORDS;
#pragma unroll
            for (int it = 0; it < 4; it++) {
                uint32_t* d = &Asn[(arow + it * 32) * APITCH + acol];
                d[0] = f32_to_tf32(av[it].x); d[1] = f32_to_tf32(av[it].y);
                d[2] = f32_to_tf32(av[it].z); d[3] = f32_to_tf32(av[it].w);
            }
#pragma unroll
            for (int it = 0; it < 2; it++) {
                uint32_t* d = &Bsn[(brow + it * 32) * APITCH + bcol];
                d[0] = f32_to_tf32(bv[it].x); d[1] = f32_to_tf32(bv[it].y);
                d[2] = f32_to_tf32(bv[it].z); d[3] = f32_to_tf32(bv[it].w);
            }
            __syncthreads();
        }
        buf ^= 1;
    }

#pragma unroll
    for (int mt = 0; mt < 2; mt++) {
#pragma unroll
        for (int nt = 0; nt < 4; nt++) {
            int col = n0 + wn * 32 + nt * 8 + tg * 2;
            float b0 = bias[col], b1 = bias[col + 1];
            float s0 = (col     < scaleCols) ? scale : 1.f;
            float s1 = (col + 1 < scaleCols) ? scale : 1.f;
            int r0 = m0 + wm * 32 + mt * 16 + grp;
            float2 v0 = make_float2((c[mt][nt][0] + b0) * s0,
                                    (c[mt][nt][1] + b1) * s1);
            float2 v1 = make_float2((c[mt][nt][2] + b0) * s0,
                                    (c[mt][nt][3] + b1) * s1);
            *(float2*)&C[(size_t)r0 * N + col]       = v0;
            *(float2*)&C[(size_t)(r0 + 8) * N + col] = v1;
        }
    }
}

// ---------------------------------------------------------------------------
// Bias pre-gather
// ---------------------------------------------------------------------------
__global__ void bias_gather_kernel(const float* __restrict__ table,
                                   const int* __restrict__ pos)
{
    const int w = blockIdx.x, h = blockIdx.y;
    float* dst = g_biasg + (size_t)(h * TOW + w) * (NWIN * NWIN);
    for (int idx = threadIdx.x; idx < NWIN * NWIN; idx += blockDim.x) {
        int p = pos[idx];
        dst[idx] = table[((size_t)p * TOW + w) * NHEADS + h];
    }
}

// ---------------------------------------------------------------------------
// Flash-style attention v7: one CTA per (b,w,h,seg), 48 query rows, 96 thr.
// S lives entirely in REGISTERS (18 n-tiles x 4 accs per lane). Softmax in
// registers via quad shuffles. P re-laid C-frag -> A-frag with index shuffles.
// smem = single 23KB union buffer: K (pitch 36) for QK^T, then V (pitch 40).
// ---------------------------------------------------------------------------
#define ATTN_THREADS 96
#define SEG_ROWS 48
#define NSEG 3
#define KP  36
#define VP  40
#define ATTN_SMEM_B (NWIN * VP * 4)   // 23040 B

__global__ __launch_bounds__(ATTN_THREADS)
void attn_mma_kernel()
{
    extern __shared__ uint32_t KV[];

    const int w = blockIdx.x, b = blockIdx.y;
    const int h = blockIdx.z / NSEG, seg = blockIdx.z % NSEG;
    const int tid  = threadIdx.x;
    const int warp = tid >> 5, lane = tid & 31;
    const int grp  = lane >> 2, tg = lane & 3;
    const int rb   = seg * SEG_ROWS + warp * 16;   // query row base (this warp)

    const size_t base = (size_t)(b * TOW + w) * NWIN * QKV_N + h * HD;
    const float* __restrict__ Qg = g_qkv + base;
    const float* __restrict__ Kg = Qg + 192;
    const float* __restrict__ Vg = Qg + 384;

    // --- phase 1: stage K (pitch 36, coalesced float4) ---
    for (int idx = tid; idx < NWIN * 8; idx += ATTN_THREADS) {
        const int i = idx >> 3, e0 = (idx & 7) * 4;
        float4 kk = *(const float4*)&Kg[(size_t)i * QKV_N + e0];
        uint32_t* kd = &KV[i * KP + e0];
        kd[0] = f32_to_tf32(kk.x); kd[1] = f32_to_tf32(kk.y);
        kd[2] = f32_to_tf32(kk.z); kd[3] = f32_to_tf32(kk.w);
    }
    // Q fragments from global
    uint32_t aq[4][4];
#pragma unroll
    for (int kt = 0; kt < 4; kt++) {
        const int k8 = kt * 8;
        aq[kt][0] = f32_to_tf32(Qg[(size_t)(rb + grp) * QKV_N + k8 + tg]);
        aq[kt][1] = f32_to_tf32(Qg[(size_t)(rb + grp + 8) * QKV_N + k8 + tg]);
        aq[kt][2] = f32_to_tf32(Qg[(size_t)(rb + grp) * QKV_N + k8 + tg + 4]);
        aq[kt][3] = f32_to_tf32(Qg[(size_t)(rb + grp + 8) * QKV_N + k8 + tg + 4]);
    }
    __syncthreads();

    // --- phase 2: S = Q K^T + bias, accumulated in registers ---
    const float* bptr = g_biasg + (size_t)(h * TOW + w) * (NWIN * NWIN);
    float sc[18][4];
#pragma unroll
    for (int nt = 0; nt < 18; nt++) {
        const int nb = nt * 8;
        float c0 = 0.f, c1 = 0.f, c2 = 0.f, c3 = 0.f;
#pragma unroll
        for (int kt = 0; kt < 4; kt++) {
            const int k8 = kt * 8;
            uint32_t b0 = KV[(nb + grp) * KP + k8 + tg];
            uint32_t b1 = KV[(nb + grp) * KP + k8 + tg + 4];
            mma_tf32_16x8x8(c0, c1, c2, c3,
                            aq[kt][0], aq[kt][1], aq[kt][2], aq[kt][3], b0, b1);
        }
        const int col = nb + tg * 2;
        float2 bv0 = *(const float2*)&bptr[(rb + grp) * NWIN + col];
        float2 bv1 = *(const float2*)&bptr[(rb + grp + 8) * NWIN + col];
        sc[nt][0] = c0 + bv0.x; sc[nt][1] = c1 + bv0.y;
        sc[nt][2] = c2 + bv1.x; sc[nt][3] = c3 + bv1.y;
    }
    __syncthreads();   // all warps done reading K; buffer free for V

    // --- phase 3: stage V (pitch 40) + in-register softmax ---
    for (int idx = tid; idx < NWIN * 8; idx += ATTN_THREADS) {
        const int i = idx >> 3, e0 = (idx & 7) * 4;
        float4 vv = *(const float4*)&Vg[(size_t)i * QKV_N + e0];
        uint32_t* vd = &KV[i * VP + e0];
        vd[0] = f32_to_tf32(vv.x); vd[1] = f32_to_tf32(vv.y);
        vd[2] = f32_to_tf32(vv.z); vd[3] = f32_to_tf32(vv.w);
    }
    {
        // row rb+grp lives in sc[*][0..1]; row rb+grp+8 in sc[*][2..3].
        float mx0 = -1e30f, mx1 = -1e30f;
#pragma unroll
        for (int nt = 0; nt < 18; nt++) {
            mx0 = fmaxf(mx0, fmaxf(sc[nt][0], sc[nt][1]));
            mx1 = fmaxf(mx1, fmaxf(sc[nt][2], sc[nt][3]));
        }
        mx0 = fmaxf(mx0, __shfl_xor_sync(0xffffffffu, mx0, 1));
        mx0 = fmaxf(mx0, __shfl_xor_sync(0xffffffffu, mx0, 2));
        mx1 = fmaxf(mx1, __shfl_xor_sync(0xffffffffu, mx1, 1));
        mx1 = fmaxf(mx1, __shfl_xor_sync(0xffffffffu, mx1, 2));
        float s0 = 0.f, s1 = 0.f;
#pragma unroll
        for (int nt = 0; nt < 18; nt++) {
            sc[nt][0] = __expf(sc[nt][0] - mx0); s0 += sc[nt][0];
            sc[nt][1] = __expf(sc[nt][1] - mx0); s0 += sc[nt][1];
            sc[nt][2] = __expf(sc[nt][2] - mx1); s1 += sc[nt][2];
            sc[nt][3] = __expf(sc[nt][3] - mx1); s1 += sc[nt][3];
        }
        s0 += __shfl_xor_sync(0xffffffffu, s0, 1);
        s0 += __shfl_xor_sync(0xffffffffu, s0, 2);
        s1 += __shfl_xor_sync(0xffffffffu, s1, 1);
        s1 += __shfl_xor_sync(0xffffffffu, s1, 2);
        const float inv0 = 1.f / s0, inv1 = 1.f / s1;
#pragma unroll
        for (int nt = 0; nt < 18; nt++) {
            sc[nt][0] = __uint_as_float(f32_to_tf32(sc[nt][0] * inv0));
            sc[nt][1] = __uint_as_float(f32_to_tf32(sc[nt][1] * inv0));
            sc[nt][2] = __uint_as_float(f32_to_tf32(sc[nt][2] * inv1));
            sc[nt][3] = __uint_as_float(f32_to_tf32(sc[nt][3] * inv1));
        }
    }
    __syncthreads();   // V staged

    // --- phase 4: O = P V; P C-frag -> A-frag via index shuffles ---
    float c[4][4];
#pragma unroll
    for (int nt = 0; nt < 4; nt++)
#pragma unroll
        for (int r = 0; r < 4; r++) c[nt][r] = 0.f;

    const int src0 = (lane & ~3) | (tg >> 1);   // quad-lane tg/2
    const int src1 = src0 + 2;                  // quad-lane tg/2 + 2
    const bool odd = (tg & 1);

#pragma unroll
    for (int kk = 0; kk < 18; kk++) {
        const int k8 = kk * 8;
        // row rb+grp (regs 0,1) -> a0 (col tg), a2 (col tg+4)
        float e0 = __shfl_sync(0xffffffffu, sc[kk][0], src0);
        float e1 = __shfl_sync(0xffffffffu, sc[kk][1], src0);
        float f0 = __shfl_sync(0xffffffffu, sc[kk][0], src1);
        float f1 = __shfl_sync(0xffffffffu, sc[kk][1], src1);
        uint32_t a0 = __float_as_uint(odd ? e1 : e0);
        uint32_t a2 = __float_as_uint(odd ? f1 : f0);
        // row rb+grp+8 (regs 2,3) -> a1, a3
        float g0 = __shfl_sync(0xffffffffu, sc[kk][2], src0);
        float g1 = __shfl_sync(0xffffffffu, sc[kk][3], src0);
        float h0 = __shfl_sync(0xffffffffu, sc[kk][2], src1);
        float h1 = __shfl_sync(0xffffffffu, sc[kk][3], src1);
        uint32_t a1 = __float_as_uint(odd ? g1 : g0);
        uint32_t a3 = __float_as_uint(odd ? h1 : h0);
#pragma unroll
        for (int nt = 0; nt < 4; nt++) {
            uint32_t b0 = KV[(k8 + tg) * VP + nt * 8 + grp];
            uint32_t b1 = KV[(k8 + tg + 4) * VP + nt * 8 + grp];
            mma_tf32_16x8x8(c[nt][0], c[nt][1], c[nt][2], c[nt][3],
                            a0, a1, a2, a3, b0, b1);
        }
    }

    const size_t obase = (size_t)(b * TOW + w) * NWIN * DIMC + h * HD;
#pragma unroll
    for (int nt = 0; nt < 4; nt++) {
        const int col = nt * 8 + tg * 2;
        *(float2*)&g_att[obase + (size_t)(rb + grp) * DIMC + col] =
            make_float2(c[nt][0], c[nt][1]);
        *(float2*)&g_att[obase + (size_t)(rb + grp + 8) * DIMC + col] =
            make_float2(c[nt][2], c[nt][3]);
    }
}

// ---------------------------------------------------------------------------
extern "C" void kernel_launch(void* const* d_in, const int* in_sizes, int n_in,
                              void* d_out, int out_size)
{
    const float* x      = (const float*)d_in[0];
    const float* qkv_w  = (const float*)d_in[1];
    const float* qkv_b  = (const float*)d_in[2];
    const float* proj_w = (const float*)d_in[3];
    const float* proj_b = (const float*)d_in[4];
    const float* table  = (const float*)d_in[5];
    const int*   pos    = (const int*)d_in[6];
    float* out = (float*)d_out;

    float *qkv_s, *att_s;
    cudaGetSymbolAddress((void**)&qkv_s, g_qkv);
    cudaGetSymbolAddress((void**)&att_s, g_att);

    cudaFuncSetAttribute(gemm_mma_kernel, cudaFuncAttributeMaxDynamicSharedMemorySize,
                         GEMM_SMEM_B);
    cudaFuncSetAttribute(attn_mma_kernel, cudaFuncAttributeMaxDynamicSharedMemorySize,
                         ATTN_SMEM_B);

    // 1) fused QKV projection (mma.sync tf32; +bias, q scaled)
    {
        dim3 grid(QKV_N / 64, MTOT / 128);
        gemm_mma_kernel<<<grid, 256, GEMM_SMEM_B>>>(x, qkv_w, qkv_b, qkv_s,
                                                    QKV_N, DIMC, DIMC, ATT_SCALE);
    }
    // 2) bias pre-gather
    {
        dim3 grid(TOW, NHEADS);
        bias_gather_kernel<<<grid, 256>>>(table, pos);
    }
    // 3) windowed attention (register-resident S, flash-style)
    {
        dim3 grid(TOW, BATCH, NHEADS * NSEG);
        attn_mma_kernel<<<grid, ATTN_THREADS, ATTN_SMEM_B>>>();
    }
    // 4) output projection (mma.sync tf32)
    {
        dim3 grid(DIMC / 64, MTOT / 128);
        gemm_mma_kernel<<<grid, 256, GEMM_SMEM_B>>>(att_s, proj_w, proj_b, out,
                                                    DIMC, DIMC, 0, 1.0f);
    }
}

// round 10
// speedup vs baseline: 2.5914x; 1.1868x over previous
#include <cuda_runtime.h>
#include <cuda_bf16.h>
#include <cstdint>

// Problem constants
#define DIMC    192
#define QKV_N   576
#define NWIN    144
#define NHEADS  6
#define HD      32
#define TOW     64
#define BATCH   30
#define MTOT    (BATCH * TOW * NWIN)   // 276480 rows
#define ATT_SCALE 0.17677669529663687f

// Scratch
static __device__ float g_qkv[(size_t)MTOT * QKV_N];   // tf32-rounded
static __device__ float g_att[(size_t)MTOT * DIMC];    // tf32-rounded
static __device__ float g_xt[(size_t)MTOT * DIMC];     // tf32-rounded x
static __device__ float g_wq[(size_t)QKV_N * DIMC];    // tf32-rounded qkv_w
static __device__ float g_wp[(size_t)DIMC * DIMC];     // tf32-rounded proj_w
static __device__ float g_biasg[(size_t)NHEADS * TOW * NWIN * NWIN];

// ---------------------------------------------------------------------------
// helpers
// ---------------------------------------------------------------------------
__device__ __forceinline__ uint32_t f32_to_tf32(float x) {
    uint32_t r;
    asm("cvt.rna.tf32.f32 %0, %1;" : "=r"(r) : "f"(x));
    return r;
}
__device__ __forceinline__ uint32_t smem_u32(const void* p) {
    uint32_t a;
    asm("{ .reg .u64 t; cvta.to.shared.u64 t, %1; cvt.u32.u64 %0, t; }"
        : "=r"(a) : "l"(p));
    return a;
}
__device__ __forceinline__ void cp16(uint32_t saddr, const void* g) {
    asm volatile("cp.async.cg.shared.global [%0], [%1], 16;"
                 :: "r"(saddr), "l"(g));
}
#define CP_COMMIT() asm volatile("cp.async.commit_group;" ::: "memory")
#define CP_WAIT(n)  asm volatile("cp.async.wait_group %0;" :: "n"(n) : "memory")

__device__ __forceinline__ void mma_tf32_16x8x8(
    float& c0, float& c1, float& c2, float& c3,
    uint32_t a0, uint32_t a1, uint32_t a2, uint32_t a3,
    uint32_t b0, uint32_t b1)
{
    asm volatile(
        "mma.sync.aligned.m16n8k8.row.col.f32.tf32.tf32.f32 "
        "{%0,%1,%2,%3}, {%4,%5,%6,%7}, {%8,%9}, {%0,%1,%2,%3};"
        : "+f"(c0), "+f"(c1), "+f"(c2), "+f"(c3)
        : "r"(a0), "r"(a1), "r"(a2), "r"(a3), "r"(b0), "r"(b1));
}

// ---------------------------------------------------------------------------
// Elementwise tf32 pre-round (vectorized)
// ---------------------------------------------------------------------------
__global__ void cvt_tf32_kernel(const float* __restrict__ in,
                                float* __restrict__ out, int n4)
{
    int i = blockIdx.x * blockDim.x + threadIdx.x;
    if (i < n4) {
        float4 v = ((const float4*)in)[i];
        v.x = __uint_as_float(f32_to_tf32(v.x));
        v.y = __uint_as_float(f32_to_tf32(v.y));
        v.z = __uint_as_float(f32_to_tf32(v.z));
        v.w = __uint_as_float(f32_to_tf32(v.w));
        ((float4*)out)[i] = v;
    }
}

// ---------------------------------------------------------------------------
// tf32 GEMM, 3-stage cp.async pipeline. Inputs pre-rounded to tf32 bits.
// C[M,N] = A[M,192] @ B[N,192]^T + bias[N]; cols<scaleCols *= scale;
// if roundOut, output is tf32-rounded.
// CTA 128x64, BK=32, 256 thr (8 warps 4x2), warp tile 32x32.
// ---------------------------------------------------------------------------
#define GKK 192
#define KITERS 6
#define APITCH 36
#define AS_WORDS (128 * APITCH)
#define BS_WORDS (64 * APITCH)
#define STAGE_WORDS (AS_WORDS + BS_WORDS)          // 6912
#define GEMM_SMEM_B (3 * STAGE_WORDS * 4)          // 82944

__global__ __launch_bounds__(256)
void gemm_tc_kernel(const float* __restrict__ A, const float* __restrict__ B,
                    const float* __restrict__ bias, float* __restrict__ C,
                    int N, int scaleCols, float scale, int roundOut)
{
    extern __shared__ uint32_t gsm[];

    const int tid  = threadIdx.x;
    const int warp = tid >> 5, lane = tid & 31;
    const int wm   = warp & 3, wn = warp >> 2;
    const int grp  = lane >> 2, tg = lane & 3;
    const int n0   = blockIdx.x * 64;
    const int m0   = blockIdx.y * 128;

    const float* Ag = A + (size_t)m0 * GKK;
    const float* Bg = B + (size_t)n0 * GKK;
    const int crow = tid >> 3, ccol = (tid & 7) * 4;
    const uint32_t sbase = smem_u32(gsm);

    // copy one 32-wide K slab into stage s
    auto issue_copy = [&](int s, int ki) {
        const int k0 = ki * 32;
        uint32_t abase = sbase + (uint32_t)(s * STAGE_WORDS) * 4;
        uint32_t bbase = abase + AS_WORDS * 4;
#pragma unroll
        for (int it = 0; it < 4; it++)
            cp16(abase + ((crow + it * 32) * APITCH + ccol) * 4,
                 &Ag[(size_t)(crow + it * 32) * GKK + k0 + ccol]);
#pragma unroll
        for (int it = 0; it < 2; it++)
            cp16(bbase + ((crow + it * 32) * APITCH + ccol) * 4,
                 &Bg[(size_t)(crow + it * 32) * GKK + k0 + ccol]);
        CP_COMMIT();
    };

    float c[2][4][4];
#pragma unroll
    for (int mt = 0; mt < 2; mt++)
#pragma unroll
        for (int nt = 0; nt < 4; nt++)
#pragma unroll
            for (int r = 0; r < 4; r++) c[mt][nt][r] = 0.f;

    issue_copy(0, 0);
    issue_copy(1, 1);

#pragma unroll
    for (int i = 0; i < KITERS; i++) {
        if (i < KITERS - 1) { CP_WAIT(1); } else { CP_WAIT(0); }
        __syncthreads();

        const uint32_t* As = gsm + (i % 3) * STAGE_WORDS;
        const uint32_t* Bs = As + AS_WORDS;
#pragma unroll
        for (int ks = 0; ks < 4; ks++) {
            const int k8 = ks * 8;
            uint32_t a[2][4];
#pragma unroll
            for (int mt = 0; mt < 2; mt++) {
                int rbw = wm * 32 + mt * 16;
                a[mt][0] = As[(rbw + grp) * APITCH + k8 + tg];
                a[mt][1] = As[(rbw + grp + 8) * APITCH + k8 + tg];
                a[mt][2] = As[(rbw + grp) * APITCH + k8 + tg + 4];
                a[mt][3] = As[(rbw + grp + 8) * APITCH + k8 + tg + 4];
            }
#pragma unroll
            for (int nt = 0; nt < 4; nt++) {
                int nb = wn * 32 + nt * 8;
                uint32_t b0 = Bs[(nb + grp) * APITCH + k8 + tg];
                uint32_t b1 = Bs[(nb + grp) * APITCH + k8 + tg + 4];
#pragma unroll
                for (int mt = 0; mt < 2; mt++)
                    mma_tf32_16x8x8(c[mt][nt][0], c[mt][nt][1],
                                    c[mt][nt][2], c[mt][nt][3],
                                    a[mt][0], a[mt][1], a[mt][2], a[mt][3],
                                    b0, b1);
            }
        }
        if (i + 2 < KITERS) issue_copy((i + 2) % 3, i + 2);
    }

#pragma unroll
    for (int mt = 0; mt < 2; mt++) {
#pragma unroll
        for (int nt = 0; nt < 4; nt++) {
            int col = n0 + wn * 32 + nt * 8 + tg * 2;
            float b0 = bias[col], b1 = bias[col + 1];
            float s0 = (col     < scaleCols) ? scale : 1.f;
            float s1 = (col + 1 < scaleCols) ? scale : 1.f;
            int r0 = m0 + wm * 32 + mt * 16 + grp;
            float v00 = (c[mt][nt][0] + b0) * s0;
            float v01 = (c[mt][nt][1] + b1) * s1;
            float v10 = (c[mt][nt][2] + b0) * s0;
            float v11 = (c[mt][nt][3] + b1) * s1;
            if (roundOut) {
                v00 = __uint_as_float(f32_to_tf32(v00));
                v01 = __uint_as_float(f32_to_tf32(v01));
                v10 = __uint_as_float(f32_to_tf32(v10));
                v11 = __uint_as_float(f32_to_tf32(v11));
            }
            *(float2*)&C[(size_t)r0 * N + col]       = make_float2(v00, v01);
            *(float2*)&C[(size_t)(r0 + 8) * N + col] = make_float2(v10, v11);
        }
    }
}

// ---------------------------------------------------------------------------
// Bias pre-gather
// ---------------------------------------------------------------------------
__global__ void bias_gather_kernel(const float* __restrict__ table,
                                   const int* __restrict__ pos)
{
    const int w = blockIdx.x, h = blockIdx.y;
    float* dst = g_biasg + (size_t)(h * TOW + w) * (NWIN * NWIN);
    for (int idx = threadIdx.x; idx < NWIN * NWIN; idx += blockDim.x) {
        int p = pos[idx];
        dst[idx] = table[((size_t)p * TOW + w) * NHEADS + h];
    }
}

// ---------------------------------------------------------------------------
// Flash-style attention v8: register-resident S, cp.async K/V staging,
// deferred softmax normalization. One CTA per (b,w,h,seg); 96 thr, 3 warps.
// g_qkv is tf32-pre-rounded; output written tf32-rounded for the proj GEMM.
// ---------------------------------------------------------------------------
#define ATTN_THREADS 96
#define SEG_ROWS 48
#define NSEG 3
#define KP  36
#define VP  40
#define ATTN_SMEM_B (NWIN * VP * 4)   // 23040 B

__global__ __launch_bounds__(ATTN_THREADS)
void attn_mma_kernel()
{
    extern __shared__ uint32_t KV[];

    const int w = blockIdx.x, b = blockIdx.y;
    const int h = blockIdx.z / NSEG, seg = blockIdx.z % NSEG;
    const int tid  = threadIdx.x;
    const int warp = tid >> 5, lane = tid & 31;
    const int grp  = lane >> 2, tg = lane & 3;
    const int rb   = seg * SEG_ROWS + warp * 16;

    const size_t base = (size_t)(b * TOW + w) * NWIN * QKV_N + h * HD;
    const float* __restrict__ Qg = g_qkv + base;
    const float* __restrict__ Kg = Qg + 192;
    const float* __restrict__ Vg = Qg + 384;
    const uint32_t kvbase = smem_u32(KV);

    // --- phase 1: cp.async K (pitch 36) ---
    for (int idx = tid; idx < NWIN * 8; idx += ATTN_THREADS) {
        const int i = idx >> 3, e0 = (idx & 7) * 4;
        cp16(kvbase + (i * KP + e0) * 4, &Kg[(size_t)i * QKV_N + e0]);
    }
    CP_COMMIT();

    // Q fragments (pre-rounded; plain loads)
    uint32_t aq[4][4];
#pragma unroll
    for (int kt = 0; kt < 4; kt++) {
        const int k8 = kt * 8;
        aq[kt][0] = __float_as_uint(Qg[(size_t)(rb + grp) * QKV_N + k8 + tg]);
        aq[kt][1] = __float_as_uint(Qg[(size_t)(rb + grp + 8) * QKV_N + k8 + tg]);
        aq[kt][2] = __float_as_uint(Qg[(size_t)(rb + grp) * QKV_N + k8 + tg + 4]);
        aq[kt][3] = __float_as_uint(Qg[(size_t)(rb + grp + 8) * QKV_N + k8 + tg + 4]);
    }
    CP_WAIT(0);
    __syncthreads();

    // --- phase 2: S = Q K^T + bias (registers) ---
    const float* bptr = g_biasg + (size_t)(h * TOW + w) * (NWIN * NWIN);
    float sc[18][4];
#pragma unroll 3
    for (int nt = 0; nt < 18; nt++) {
        const int nb = nt * 8;
        float c0 = 0.f, c1 = 0.f, c2 = 0.f, c3 = 0.f;
#pragma unroll
        for (int kt = 0; kt < 4; kt++) {
            const int k8 = kt * 8;
            uint32_t b0 = KV[(nb + grp) * KP + k8 + tg];
            uint32_t b1 = KV[(nb + grp) * KP + k8 + tg + 4];
            mma_tf32_16x8x8(c0, c1, c2, c3,
                            aq[kt][0], aq[kt][1], aq[kt][2], aq[kt][3], b0, b1);
        }
        const int col = nb + tg * 2;
        float2 bv0 = *(const float2*)&bptr[(rb + grp) * NWIN + col];
        float2 bv1 = *(const float2*)&bptr[(rb + grp + 8) * NWIN + col];
        sc[nt][0] = c0 + bv0.x; sc[nt][1] = c1 + bv0.y;
        sc[nt][2] = c2 + bv1.x; sc[nt][3] = c3 + bv1.y;
    }
    __syncthreads();   // K fully consumed; buffer free for V

    // --- phase 3: cp.async V (pitch 40), overlapped with softmax ---
    for (int idx = tid; idx < NWIN * 8; idx += ATTN_THREADS) {
        const int i = idx >> 3, e0 = (idx & 7) * 4;
        cp16(kvbase + (i * VP + e0) * 4, &Vg[(size_t)i * QKV_N + e0]);
    }
    CP_COMMIT();

    float inv0, inv1;
    {
        float mx0 = -1e30f, mx1 = -1e30f;
#pragma unroll
        for (int nt = 0; nt < 18; nt++) {
            mx0 = fmaxf(mx0, fmaxf(sc[nt][0], sc[nt][1]));
            mx1 = fmaxf(mx1, fmaxf(sc[nt][2], sc[nt][3]));
        }
        mx0 = fmaxf(mx0, __shfl_xor_sync(0xffffffffu, mx0, 1));
        mx0 = fmaxf(mx0, __shfl_xor_sync(0xffffffffu, mx0, 2));
        mx1 = fmaxf(mx1, __shfl_xor_sync(0xffffffffu, mx1, 1));
        mx1 = fmaxf(mx1, __shfl_xor_sync(0xffffffffu, mx1, 2));
        float s0 = 0.f, s1 = 0.f;
#pragma unroll
        for (int nt = 0; nt < 18; nt++) {
            sc[nt][0] = __expf(sc[nt][0] - mx0); s0 += sc[nt][0];
            sc[nt][1] = __expf(sc[nt][1] - mx0); s0 += sc[nt][1];
            sc[nt][2] = __expf(sc[nt][2] - mx1); s1 += sc[nt][2];
            sc[nt][3] = __expf(sc[nt][3] - mx1); s1 += sc[nt][3];
        }
        s0 += __shfl_xor_sync(0xffffffffu, s0, 1);
        s0 += __shfl_xor_sync(0xffffffffu, s0, 2);
        s1 += __shfl_xor_sync(0xffffffffu, s1, 1);
        s1 += __shfl_xor_sync(0xffffffffu, s1, 2);
        inv0 = 1.f / s0; inv1 = 1.f / s1;
        // round unnormalized P to tf32 (normalization deferred to epilogue)
#pragma unroll
        for (int nt = 0; nt < 18; nt++) {
            sc[nt][0] = __uint_as_float(f32_to_tf32(sc[nt][0]));
            sc[nt][1] = __uint_as_float(f32_to_tf32(sc[nt][1]));
            sc[nt][2] = __uint_as_float(f32_to_tf32(sc[nt][2]));
            sc[nt][3] = __uint_as_float(f32_to_tf32(sc[nt][3]));
        }
    }
    CP_WAIT(0);
    __syncthreads();   // V staged

    // --- phase 4: O = P V; P C-frag -> A-frag via index shuffles ---
    float c[4][4];
#pragma unroll
    for (int nt = 0; nt < 4; nt++)
#pragma unroll
        for (int r = 0; r < 4; r++) c[nt][r] = 0.f;

    const int src0 = (lane & ~3) | (tg >> 1);
    const int src1 = src0 + 2;
    const bool odd = (tg & 1);

#pragma unroll 3
    for (int kk = 0; kk < 18; kk++) {
        const int k8 = kk * 8;
        float e0 = __shfl_sync(0xffffffffu, sc[kk][0], src0);
        float e1 = __shfl_sync(0xffffffffu, sc[kk][1], src0);
        float f0 = __shfl_sync(0xffffffffu, sc[kk][0], src1);
        float f1 = __shfl_sync(0xffffffffu, sc[kk][1], src1);
        uint32_t a0 = __float_as_uint(odd ? e1 : e0);
        uint32_t a2 = __float_as_uint(odd ? f1 : f0);
        float g0 = __shfl_sync(0xffffffffu, sc[kk][2], src0);
        float g1 = __shfl_sync(0xffffffffu, sc[kk][3], src0);
        float h0 = __shfl_sync(0xffffffffu, sc[kk][2], src1);
        float h1 = __shfl_sync(0xffffffffu, sc[kk][3], src1);
        uint32_t a1 = __float_as_uint(odd ? g1 : g0);
        uint32_t a3 = __float_as_uint(odd ? h1 : h0);
#pragma unroll
        for (int nt = 0; nt < 4; nt++) {
            uint32_t b0 = KV[(k8 + tg) * VP + nt * 8 + grp];
            uint32_t b1 = KV[(k8 + tg + 4) * VP + nt * 8 + grp];
            mma_tf32_16x8x8(c[nt][0], c[nt][1], c[nt][2], c[nt][3],
                            a0, a1, a2, a3, b0, b1);
        }
    }

    // epilogue: normalize by row sums, round to tf32 for the proj GEMM
    const size_t obase = (size_t)(b * TOW + w) * NWIN * DIMC + h * HD;
#pragma unroll
    for (int nt = 0; nt < 4; nt++) {
        const int col = nt * 8 + tg * 2;
        float o00 = __uint_as_float(f32_to_tf32(c[nt][0] * inv0));
        float o01 = __uint_as_float(f32_to_tf32(c[nt][1] * inv0));
        float o10 = __uint_as_float(f32_to_tf32(c[nt][2] * inv1));
        float o11 = __uint_as_float(f32_to_tf32(c[nt][3] * inv1));
        *(float2*)&g_att[obase + (size_t)(rb + grp) * DIMC + col] =
            make_float2(o00, o01);
        *(float2*)&g_att[obase + (size_t)(rb + grp + 8) * DIMC + col] =
            make_float2(o10, o11);
    }
}

// ---------------------------------------------------------------------------
extern "C" void kernel_launch(void* const* d_in, const int* in_sizes, int n_in,
                              void* d_out, int out_size)
{
    const float* x      = (const float*)d_in[0];
    const float* qkv_w  = (const float*)d_in[1];
    const float* qkv_b  = (const float*)d_in[2];
    const float* proj_w = (const float*)d_in[3];
    const float* proj_b = (const float*)d_in[4];
    const float* table  = (const float*)d_in[5];
    const int*   pos    = (const int*)d_in[6];
    float* out = (float*)d_out;

    float *qkv_s, *att_s, *xt_s, *wq_s, *wp_s;
    cudaGetSymbolAddress((void**)&qkv_s, g_qkv);
    cudaGetSymbolAddress((void**)&att_s, g_att);
    cudaGetSymbolAddress((void**)&xt_s,  g_xt);
    cudaGetSymbolAddress((void**)&wq_s,  g_wq);
    cudaGetSymbolAddress((void**)&wp_s,  g_wp);

    cudaFuncSetAttribute(gemm_tc_kernel, cudaFuncAttributeMaxDynamicSharedMemorySize,
                         GEMM_SMEM_B);
    cudaFuncSetAttribute(attn_mma_kernel, cudaFuncAttributeMaxDynamicSharedMemorySize,
                         ATTN_SMEM_B);

    // 0) pre-round inputs to tf32
    {
        int n4 = MTOT * DIMC / 4;
        cvt_tf32_kernel<<<(n4 + 255) / 256, 256>>>(x, xt_s, n4);
        int w4 = QKV_N * DIMC / 4;
        cvt_tf32_kernel<<<(w4 + 255) / 256, 256>>>(qkv_w, wq_s, w4);
        int p4 = DIMC * DIMC / 4;
        cvt_tf32_kernel<<<(p4 + 255) / 256, 256>>>(proj_w, wp_s, p4);
    }
    // 1) bias pre-gather
    {
        dim3 grid(TOW, NHEADS);
        bias_gather_kernel<<<grid, 256>>>(table, pos);
    }
    // 2) fused QKV projection (+bias, q scaled, tf32-rounded output)
    {
        dim3 grid(QKV_N / 64, MTOT / 128);
        gemm_tc_kernel<<<grid, 256, GEMM_SMEM_B>>>(xt_s, wq_s, qkv_b, qkv_s,
                                                   QKV_N, DIMC, ATT_SCALE, 1);
    }
    // 3) windowed attention
    {
        dim3 grid(TOW, BATCH, NHEADS * NSEG);
        attn_mma_kernel<<<grid, ATTN_THREADS, ATTN_SMEM_B>>>();
    }
    // 4) output projection (fp32 output)
    {
        dim3 grid(DIMC / 64, MTOT / 128);
        gemm_tc_kernel<<<grid, 256, GEMM_SMEM_B>>>(att_s, wp_s, proj_b, out,
                                                   DIMC, 0, 1.0f, 0);
    }
}

// round 11
// speedup vs baseline: 2.7135x; 1.0472x over previous
#include <cuda_runtime.h>
#include <cuda_bf16.h>
#include <cstdint>

// Problem constants
#define DIMC    192
#define QKV_N   576
#define NWIN    144
#define NHEADS  6
#define HD      32
#define TOW     64
#define BATCH   30
#define MTOT    (BATCH * TOW * NWIN)   // 276480 rows
#define ATT_SCALE 0.17677669529663687f

// Scratch
static __device__ float g_qkv[(size_t)MTOT * QKV_N];   // tf32-rounded
static __device__ float g_att[(size_t)MTOT * DIMC];    // tf32-rounded
static __device__ float g_xt[(size_t)MTOT * DIMC];     // tf32-rounded x
static __device__ float g_wq[(size_t)QKV_N * DIMC];    // tf32-rounded qkv_w
static __device__ float g_wp[(size_t)DIMC * DIMC];     // tf32-rounded proj_w
static __device__ float g_biasg[(size_t)NHEADS * TOW * NWIN * NWIN]; // fragment-permuted

// ---------------------------------------------------------------------------
// helpers
// ---------------------------------------------------------------------------
__device__ __forceinline__ uint32_t f32_to_tf32(float x) {
    uint32_t r;
    asm("cvt.rna.tf32.f32 %0, %1;" : "=r"(r) : "f"(x));
    return r;
}
__device__ __forceinline__ uint32_t smem_u32(const void* p) {
    uint32_t a;
    asm("{ .reg .u64 t; cvta.to.shared.u64 t, %1; cvt.u32.u64 %0, t; }"
        : "=r"(a) : "l"(p));
    return a;
}
__device__ __forceinline__ void cp16(uint32_t saddr, const void* g) {
    asm volatile("cp.async.cg.shared.global [%0], [%1], 16;"
                 :: "r"(saddr), "l"(g));
}
#define CP_COMMIT() asm volatile("cp.async.commit_group;" ::: "memory")
#define CP_WAIT(n)  asm volatile("cp.async.wait_group %0;" :: "n"(n) : "memory")

__device__ __forceinline__ void mma_tf32_16x8x8(
    float& c0, float& c1, float& c2, float& c3,
    uint32_t a0, uint32_t a1, uint32_t a2, uint32_t a3,
    uint32_t b0, uint32_t b1)
{
    asm volatile(
        "mma.sync.aligned.m16n8k8.row.col.f32.tf32.tf32.f32 "
        "{%0,%1,%2,%3}, {%4,%5,%6,%7}, {%8,%9}, {%0,%1,%2,%3};"
        : "+f"(c0), "+f"(c1), "+f"(c2), "+f"(c3)
        : "r"(a0), "r"(a1), "r"(a2), "r"(a3), "r"(b0), "r"(b1));
}

// ---------------------------------------------------------------------------
// Elementwise tf32 pre-round
// ---------------------------------------------------------------------------
__global__ void cvt_tf32_kernel(const float* __restrict__ in,
                                float* __restrict__ out, int n4)
{
    int i = blockIdx.x * blockDim.x + threadIdx.x;
    if (i < n4) {
        float4 v = ((const float4*)in)[i];
        v.x = __uint_as_float(f32_to_tf32(v.x));
        v.y = __uint_as_float(f32_to_tf32(v.y));
        v.z = __uint_as_float(f32_to_tf32(v.z));
        v.w = __uint_as_float(f32_to_tf32(v.w));
        ((float4*)out)[i] = v;
    }
}

// ---------------------------------------------------------------------------
// tf32 GEMM, 3-stage cp.async pipeline (unchanged from R10).
// ---------------------------------------------------------------------------
#define GKK 192
#define KITERS 6
#define APITCH 36
#define AS_WORDS (128 * APITCH)
#define BS_WORDS (64 * APITCH)
#define STAGE_WORDS (AS_WORDS + BS_WORDS)          // 6912
#define GEMM_SMEM_B (3 * STAGE_WORDS * 4)          // 82944

__global__ __launch_bounds__(256)
void gemm_tc_kernel(const float* __restrict__ A, const float* __restrict__ B,
                    const float* __restrict__ bias, float* __restrict__ C,
                    int N, int scaleCols, float scale, int roundOut)
{
    extern __shared__ uint32_t gsm[];

    const int tid  = threadIdx.x;
    const int warp = tid >> 5, lane = tid & 31;
    const int wm   = warp & 3, wn = warp >> 2;
    const int grp  = lane >> 2, tg = lane & 3;
    const int n0   = blockIdx.x * 64;
    const int m0   = blockIdx.y * 128;

    const float* Ag = A + (size_t)m0 * GKK;
    const float* Bg = B + (size_t)n0 * GKK;
    const int crow = tid >> 3, ccol = (tid & 7) * 4;
    const uint32_t sbase = smem_u32(gsm);

    auto issue_copy = [&](int s, int ki) {
        const int k0 = ki * 32;
        uint32_t abase = sbase + (uint32_t)(s * STAGE_WORDS) * 4;
        uint32_t bbase = abase + AS_WORDS * 4;
#pragma unroll
        for (int it = 0; it < 4; it++)
            cp16(abase + ((crow + it * 32) * APITCH + ccol) * 4,
                 &Ag[(size_t)(crow + it * 32) * GKK + k0 + ccol]);
#pragma unroll
        for (int it = 0; it < 2; it++)
            cp16(bbase + ((crow + it * 32) * APITCH + ccol) * 4,
                 &Bg[(size_t)(crow + it * 32) * GKK + k0 + ccol]);
        CP_COMMIT();
    };

    float c[2][4][4];
#pragma unroll
    for (int mt = 0; mt < 2; mt++)
#pragma unroll
        for (int nt = 0; nt < 4; nt++)
#pragma unroll
            for (int r = 0; r < 4; r++) c[mt][nt][r] = 0.f;

    issue_copy(0, 0);
    issue_copy(1, 1);

#pragma unroll
    for (int i = 0; i < KITERS; i++) {
        if (i < KITERS - 1) { CP_WAIT(1); } else { CP_WAIT(0); }
        __syncthreads();

        const uint32_t* As = gsm + (i % 3) * STAGE_WORDS;
        const uint32_t* Bs = As + AS_WORDS;
#pragma unroll
        for (int ks = 0; ks < 4; ks++) {
            const int k8 = ks * 8;
            uint32_t a[2][4];
#pragma unroll
            for (int mt = 0; mt < 2; mt++) {
                int rbw = wm * 32 + mt * 16;
                a[mt][0] = As[(rbw + grp) * APITCH + k8 + tg];
                a[mt][1] = As[(rbw + grp + 8) * APITCH + k8 + tg];
                a[mt][2] = As[(rbw + grp) * APITCH + k8 + tg + 4];
                a[mt][3] = As[(rbw + grp + 8) * APITCH + k8 + tg + 4];
            }
#pragma unroll
            for (int nt = 0; nt < 4; nt++) {
                int nb = wn * 32 + nt * 8;
                uint32_t b0 = Bs[(nb + grp) * APITCH + k8 + tg];
                uint32_t b1 = Bs[(nb + grp) * APITCH + k8 + tg + 4];
#pragma unroll
                for (int mt = 0; mt < 2; mt++)
                    mma_tf32_16x8x8(c[mt][nt][0], c[mt][nt][1],
                                    c[mt][nt][2], c[mt][nt][3],
                                    a[mt][0], a[mt][1], a[mt][2], a[mt][3],
                                    b0, b1);
            }
        }
        if (i + 2 < KITERS) issue_copy((i + 2) % 3, i + 2);
    }

#pragma unroll
    for (int mt = 0; mt < 2; mt++) {
#pragma unroll
        for (int nt = 0; nt < 4; nt++) {
            int col = n0 + wn * 32 + nt * 8 + tg * 2;
            float b0 = bias[col], b1 = bias[col + 1];
            float s0 = (col     < scaleCols) ? scale : 1.f;
            float s1 = (col + 1 < scaleCols) ? scale : 1.f;
            int r0 = m0 + wm * 32 + mt * 16 + grp;
            float v00 = (c[mt][nt][0] + b0) * s0;
            float v01 = (c[mt][nt][1] + b1) * s1;
            float v10 = (c[mt][nt][2] + b0) * s0;
            float v11 = (c[mt][nt][3] + b1) * s1;
            if (roundOut) {
                v00 = __uint_as_float(f32_to_tf32(v00));
                v01 = __uint_as_float(f32_to_tf32(v01));
                v10 = __uint_as_float(f32_to_tf32(v10));
                v11 = __uint_as_float(f32_to_tf32(v11));
            }
            *(float2*)&C[(size_t)r0 * N + col]       = make_float2(v00, v01);
            *(float2*)&C[(size_t)(r0 + 8) * N + col] = make_float2(v10, v11);
        }
    }
}

// ---------------------------------------------------------------------------
// Bias pre-gather into FRAGMENT-PERMUTED layout:
// per (h,w): offset = (seg*3+warp)*2304 + nt*128 + half*64 + lane*2 + bb
// where i = seg*48+warp*16+half*8+grp, j = nt*8+tg*2+bb, lane = grp*4+tg.
// Writes are linear/coalesced; reads were random either way.
// ---------------------------------------------------------------------------
__global__ void bias_gather_kernel(const float* __restrict__ table,
                                   const int* __restrict__ pos)
{
    const int w = blockIdx.x, h = blockIdx.y;
    float* dst = g_biasg + (size_t)(h * TOW + w) * (NWIN * NWIN);
    for (int op = threadIdx.x; op < NWIN * NWIN; op += blockDim.x) {
        const int sw   = op / 2304;          // seg*3+warp
        const int rem  = op % 2304;
        const int nt   = rem / 128;
        const int rem2 = rem % 128;
        const int half = rem2 / 64;
        const int l2   = rem2 % 64;
        const int lane = l2 / 2, bb = l2 % 2;
        const int grp  = lane / 4, tg = lane % 4;
        const int i = (sw / 3) * 48 + (sw % 3) * 16 + half * 8 + grp;
        const int j = nt * 8 + tg * 2 + bb;
        const int p = pos[i * NWIN + j];
        dst[op] = table[((size_t)p * TOW + w) * NHEADS + h];
    }
}

// ---------------------------------------------------------------------------
// Flash-style attention v9: register S; Q staged in smem via cp.async;
// bias read coalesced from permuted layout. 96 thr, 3 warps, 48 rows/CTA.
// smem: KV union 23040B + Qs 6912B = 29952B
// ---------------------------------------------------------------------------
#define ATTN_THREADS 96
#define SEG_ROWS 48
#define NSEG 3
#define KP  36
#define VP  40
#define QP  36
#define KV_WORDS (NWIN * VP)                  // 5760
#define QS_OFF   KV_WORDS
#define ATTN_SMEM_B ((KV_WORDS + SEG_ROWS * QP) * 4)   // 29952

__global__ __launch_bounds__(ATTN_THREADS)
void attn_mma_kernel()
{
    extern __shared__ uint32_t smw[];
    uint32_t* KV = smw;
    uint32_t* Qs = smw + QS_OFF;

    const int w = blockIdx.x, b = blockIdx.y;
    const int h = blockIdx.z / NSEG, seg = blockIdx.z % NSEG;
    const int tid  = threadIdx.x;
    const int warp = tid >> 5, lane = tid & 31;
    const int grp  = lane >> 2, tg = lane & 3;
    const int lrb  = warp * 16;
    const int rb   = seg * SEG_ROWS + lrb;

    const size_t base = (size_t)(b * TOW + w) * NWIN * QKV_N + h * HD;
    const float* __restrict__ Qg = g_qkv + base;
    const float* __restrict__ Kg = Qg + 192;
    const float* __restrict__ Vg = Qg + 384;
    const uint32_t kvbase = smem_u32(KV);
    const uint32_t qsbase = smem_u32(Qs);

    // --- phase 1: cp.async K (pitch 36) + Q segment (pitch 36) ---
    for (int idx = tid; idx < NWIN * 8; idx += ATTN_THREADS) {
        const int i = idx >> 3, e0 = (idx & 7) * 4;
        cp16(kvbase + (i * KP + e0) * 4, &Kg[(size_t)i * QKV_N + e0]);
    }
    for (int idx = tid; idx < SEG_ROWS * 8; idx += ATTN_THREADS) {
        const int i = idx >> 3, e0 = (idx & 7) * 4;
        cp16(qsbase + (i * QP + e0) * 4,
             &Qg[(size_t)(seg * SEG_ROWS + i) * QKV_N + e0]);
    }
    CP_COMMIT();
    CP_WAIT(0);
    __syncthreads();

    // Q fragments from smem (conflict-free scalar LDS)
    uint32_t aq[4][4];
#pragma unroll
    for (int kt = 0; kt < 4; kt++) {
        const int k8 = kt * 8;
        aq[kt][0] = Qs[(lrb + grp) * QP + k8 + tg];
        aq[kt][1] = Qs[(lrb + grp + 8) * QP + k8 + tg];
        aq[kt][2] = Qs[(lrb + grp) * QP + k8 + tg + 4];
        aq[kt][3] = Qs[(lrb + grp + 8) * QP + k8 + tg + 4];
    }

    // --- phase 2: S = Q K^T + bias (registers, coalesced bias reads) ---
    const float* bptr = g_biasg + (size_t)(h * TOW + w) * (NWIN * NWIN)
                        + (size_t)(seg * 3 + warp) * 2304;
    float sc[18][4];
#pragma unroll 3
    for (int nt = 0; nt < 18; nt++) {
        const int nb = nt * 8;
        float c0 = 0.f, c1 = 0.f, c2 = 0.f, c3 = 0.f;
#pragma unroll
        for (int kt = 0; kt < 4; kt++) {
            const int k8 = kt * 8;
            uint32_t b0 = KV[(nb + grp) * KP + k8 + tg];
            uint32_t b1 = KV[(nb + grp) * KP + k8 + tg + 4];
            mma_tf32_16x8x8(c0, c1, c2, c3,
                            aq[kt][0], aq[kt][1], aq[kt][2], aq[kt][3], b0, b1);
        }
        float2 bv0 = *(const float2*)&bptr[nt * 128 + lane * 2];
        float2 bv1 = *(const float2*)&bptr[nt * 128 + 64 + lane * 2];
        sc[nt][0] = c0 + bv0.x; sc[nt][1] = c1 + bv0.y;
        sc[nt][2] = c2 + bv1.x; sc[nt][3] = c3 + bv1.y;
    }
    __syncthreads();   // K consumed; KV buffer free for V

    // --- phase 3: cp.async V (pitch 40), overlapped with softmax ---
    for (int idx = tid; idx < NWIN * 8; idx += ATTN_THREADS) {
        const int i = idx >> 3, e0 = (idx & 7) * 4;
        cp16(kvbase + (i * VP + e0) * 4, &Vg[(size_t)i * QKV_N + e0]);
    }
    CP_COMMIT();

    float inv0, inv1;
    {
        float mx0 = -1e30f, mx1 = -1e30f;
#pragma unroll
        for (int nt = 0; nt < 18; nt++) {
            mx0 = fmaxf(mx0, fmaxf(sc[nt][0], sc[nt][1]));
            mx1 = fmaxf(mx1, fmaxf(sc[nt][2], sc[nt][3]));
        }
        mx0 = fmaxf(mx0, __shfl_xor_sync(0xffffffffu, mx0, 1));
        mx0 = fmaxf(mx0, __shfl_xor_sync(0xffffffffu, mx0, 2));
        mx1 = fmaxf(mx1, __shfl_xor_sync(0xffffffffu, mx1, 1));
        mx1 = fmaxf(mx1, __shfl_xor_sync(0xffffffffu, mx1, 2));
        float s0 = 0.f, s1 = 0.f;
#pragma unroll
        for (int nt = 0; nt < 18; nt++) {
            sc[nt][0] = __expf(sc[nt][0] - mx0); s0 += sc[nt][0];
            sc[nt][1] = __expf(sc[nt][1] - mx0); s0 += sc[nt][1];
            sc[nt][2] = __expf(sc[nt][2] - mx1); s1 += sc[nt][2];
            sc[nt][3] = __expf(sc[nt][3] - mx1); s1 += sc[nt][3];
        }
        s0 += __shfl_xor_sync(0xffffffffu, s0, 1);
        s0 += __shfl_xor_sync(0xffffffffu, s0, 2);
        s1 += __shfl_xor_sync(0xffffffffu, s1, 1);
        s1 += __shfl_xor_sync(0xffffffffu, s1, 2);
        inv0 = 1.f / s0; inv1 = 1.f / s1;
#pragma unroll
        for (int nt = 0; nt < 18; nt++) {
            sc[nt][0] = __uint_as_float(f32_to_tf32(sc[nt][0]));
            sc[nt][1] = __uint_as_float(f32_to_tf32(sc[nt][1]));
            sc[nt][2] = __uint_as_float(f32_to_tf32(sc[nt][2]));
            sc[nt][3] = __uint_as_float(f32_to_tf32(sc[nt][3]));
        }
    }
    CP_WAIT(0);
    __syncthreads();   // V staged

    // --- phase 4: O = P V; P C-frag -> A-frag via index shuffles ---
    float c[4][4];
#pragma unroll
    for (int nt = 0; nt < 4; nt++)
#pragma unroll
        for (int r = 0; r < 4; r++) c[nt][r] = 0.f;

    const int src0 = (lane & ~3) | (tg >> 1);
    const int src1 = src0 + 2;
    const bool odd = (tg & 1);

#pragma unroll 3
    for (int kk = 0; kk < 18; kk++) {
        const int k8 = kk * 8;
        float e0 = __shfl_sync(0xffffffffu, sc[kk][0], src0);
        float e1 = __shfl_sync(0xffffffffu, sc[kk][1], src0);
        float f0 = __shfl_sync(0xffffffffu, sc[kk][0], src1);
        float f1 = __shfl_sync(0xffffffffu, sc[kk][1], src1);
        uint32_t a0 = __float_as_uint(odd ? e1 : e0);
        uint32_t a2 = __float_as_uint(odd ? f1 : f0);
        float g0 = __shfl_sync(0xffffffffu, sc[kk][2], src0);
        float g1 = __shfl_sync(0xffffffffu, sc[kk][3], src0);
        float h0 = __shfl_sync(0xffffffffu, sc[kk][2], src1);
        float h1 = __shfl_sync(0xffffffffu, sc[kk][3], src1);
        uint32_t a1 = __float_as_uint(odd ? g1 : g0);
        uint32_t a3 = __float_as_uint(odd ? h1 : h0);
#pragma unroll
        for (int nt = 0; nt < 4; nt++) {
            uint32_t b0 = KV[(k8 + tg) * VP + nt * 8 + grp];
            uint32_t b1 = KV[(k8 + tg + 4) * VP + nt * 8 + grp];
            mma_tf32_16x8x8(c[nt][0], c[nt][1], c[nt][2], c[nt][3],
                            a0, a1, a2, a3, b0, b1);
        }
    }

    const size_t obase = (size_t)(b * TOW + w) * NWIN * DIMC + h * HD;
#pragma unroll
    for (int nt = 0; nt < 4; nt++) {
        const int col = nt * 8 + tg * 2;
        float o00 = __uint_as_float(f32_to_tf32(c[nt][0] * inv0));
        float o01 = __uint_as_float(f32_to_tf32(c[nt][1] * inv0));
        float o10 = __uint_as_float(f32_to_tf32(c[nt][2] * inv1));
        float o11 = __uint_as_float(f32_to_tf32(c[nt][3] * inv1));
        *(float2*)&g_att[obase + (size_t)(rb + grp) * DIMC + col] =
            make_float2(o00, o01);
        *(float2*)&g_att[obase + (size_t)(rb + grp + 8) * DIMC + col] =
            make_float2(o10, o11);
    }
}

// ---------------------------------------------------------------------------
extern "C" void kernel_launch(void* const* d_in, const int* in_sizes, int n_in,
                              void* d_out, int out_size)
{
    const float* x      = (const float*)d_in[0];
    const float* qkv_w  = (const float*)d_in[1];
    const float* qkv_b  = (const float*)d_in[2];
    const float* proj_w = (const float*)d_in[3];
    const float* proj_b = (const float*)d_in[4];
    const float* table  = (const float*)d_in[5];
    const int*   pos    = (const int*)d_in[6];
    float* out = (float*)d_out;

    float *qkv_s, *att_s, *xt_s, *wq_s, *wp_s;
    cudaGetSymbolAddress((void**)&qkv_s, g_qkv);
    cudaGetSymbolAddress((void**)&att_s, g_att);
    cudaGetSymbolAddress((void**)&xt_s,  g_xt);
    cudaGetSymbolAddress((void**)&wq_s,  g_wq);
    cudaGetSymbolAddress((void**)&wp_s,  g_wp);

    cudaFuncSetAttribute(gemm_tc_kernel, cudaFuncAttributeMaxDynamicSharedMemorySize,
                         GEMM_SMEM_B);
    cudaFuncSetAttribute(attn_mma_kernel, cudaFuncAttributeMaxDynamicSharedMemorySize,
                         ATTN_SMEM_B);

    // 0) pre-round inputs to tf32
    {
        int n4 = MTOT * DIMC / 4;
        cvt_tf32_kernel<<<(n4 + 255) / 256, 256>>>(x, xt_s, n4);
        int w4 = QKV_N * DIMC / 4;
        cvt_tf32_kernel<<<(w4 + 255) / 256, 256>>>(qkv_w, wq_s, w4);
        int p4 = DIMC * DIMC / 4;
        cvt_tf32_kernel<<<(p4 + 255) / 256, 256>>>(proj_w, wp_s, p4);
    }
    // 1) bias pre-gather (fragment-permuted layout)
    {
        dim3 grid(TOW, NHEADS);
        bias_gather_kernel<<<grid, 256>>>(table, pos);
    }
    // 2) fused QKV projection
    {
        dim3 grid(QKV_N / 64, MTOT / 128);
        gemm_tc_kernel<<<grid, 256, GEMM_SMEM_B>>>(xt_s, wq_s, qkv_b, qkv_s,
                                                   QKV_N, DIMC, ATT_SCALE, 1);
    }
    // 3) windowed attention
    {
        dim3 grid(TOW, BATCH, NHEADS * NSEG);
        attn_mma_kernel<<<grid, ATTN_THREADS, ATTN_SMEM_B>>>();
    }
    // 4) output projection
    {
        dim3 grid(DIMC / 64, MTOT / 128);
        gemm_tc_kernel<<<grid, 256, GEMM_SMEM_B>>>(att_s, wp_s, proj_b, out,
                                                   DIMC, 0, 1.0f, 0);
    }
}

// round 13
// speedup vs baseline: 2.7304x; 1.0062x over previous
#include <cuda_runtime.h>
#include <cuda_bf16.h>
#include <cstdint>

// Problem constants
#define DIMC    192
#define QKV_N   576
#define NWIN    144
#define NHEADS  6
#define HD      32
#define TOW     64
#define BATCH   30
#define MTOT    (BATCH * TOW * NWIN)   // 276480 rows
#define TABLE   3312
#define ATT_SCALE 0.17677669529663687f
#define LOG2E     1.4426950408889634f

// Scratch
static __device__ float g_qkv[(size_t)MTOT * QKV_N];   // tf32-rounded; q scaled by ATT_SCALE*LOG2E
static __device__ float g_att[(size_t)MTOT * DIMC];    // tf32-rounded
static __device__ float g_xt[(size_t)MTOT * DIMC];     // tf32-rounded x
static __device__ float g_wq[(size_t)QKV_N * DIMC];    // tf32-rounded qkv_w
static __device__ float g_wp[(size_t)DIMC * DIMC];     // tf32-rounded proj_w
static __device__ float g_tableT[(size_t)TOW * NHEADS * TABLE]; // transposed, xLOG2E
static __device__ float g_biasg[(size_t)NHEADS * TOW * NWIN * NWIN]; // fragment-permuted, xLOG2E

// ---------------------------------------------------------------------------
// helpers
// ---------------------------------------------------------------------------
__device__ __forceinline__ uint32_t f32_to_tf32(float x) {
    uint32_t r;
    asm("cvt.rna.tf32.f32 %0, %1;" : "=r"(r) : "f"(x));
    return r;
}
__device__ __forceinline__ float ex2_approx(float x) {
    float r;
    asm("ex2.approx.f32 %0, %1;" : "=f"(r) : "f"(x));
    return r;
}
__device__ __forceinline__ uint32_t smem_u32(const void* p) {
    uint32_t a;
    asm("{ .reg .u64 t; cvta.to.shared.u64 t, %1; cvt.u32.u64 %0, t; }"
        : "=r"(a) : "l"(p));
    return a;
}
__device__ __forceinline__ void cp16(uint32_t saddr, const void* g) {
    asm volatile("cp.async.cg.shared.global [%0], [%1], 16;"
                 :: "r"(saddr), "l"(g));
}
#define CP_COMMIT() asm volatile("cp.async.commit_group;" ::: "memory")
#define CP_WAIT(n)  asm volatile("cp.async.wait_group %0;" :: "n"(n) : "memory")

__device__ __forceinline__ void mma_tf32_16x8x8(
    float& c0, float& c1, float& c2, float& c3,
    uint32_t a0, uint32_t a1, uint32_t a2, uint32_t a3,
    uint32_t b0, uint32_t b1)
{
    asm volatile(
        "mma.sync.aligned.m16n8k8.row.col.f32.tf32.tf32.f32 "
        "{%0,%1,%2,%3}, {%4,%5,%6,%7}, {%8,%9}, {%0,%1,%2,%3};"
        : "+f"(c0), "+f"(c1), "+f"(c2), "+f"(c3)
        : "r"(a0), "r"(a1), "r"(a2), "r"(a3), "r"(b0), "r"(b1));
}

// ---------------------------------------------------------------------------
// Elementwise tf32 pre-round
// ---------------------------------------------------------------------------
__global__ void cvt_tf32_kernel(const float* __restrict__ in,
                                float* __restrict__ out, int n4)
{
    int i = blockIdx.x * blockDim.x + threadIdx.x;
    if (i < n4) {
        float4 v = ((const float4*)in)[i];
        v.x = __uint_as_float(f32_to_tf32(v.x));
        v.y = __uint_as_float(f32_to_tf32(v.y));
        v.z = __uint_as_float(f32_to_tf32(v.z));
        v.w = __uint_as_float(f32_to_tf32(v.w));
        ((float4*)out)[i] = v;
    }
}

// ---------------------------------------------------------------------------
// tf32 GEMM, 3-stage cp.async pipeline (unchanged from R10/R11).
// ---------------------------------------------------------------------------
#define GKK 192
#define KITERS 6
#define APITCH 36
#define AS_WORDS (128 * APITCH)
#define BS_WORDS (64 * APITCH)
#define STAGE_WORDS (AS_WORDS + BS_WORDS)          // 6912
#define GEMM_SMEM_B (3 * STAGE_WORDS * 4)          // 82944

__global__ __launch_bounds__(256)
void gemm_tc_kernel(const float* __restrict__ A, const float* __restrict__ B,
                    const float* __restrict__ bias, float* __restrict__ C,
                    int N, int scaleCols, float scale, int roundOut)
{
    extern __shared__ uint32_t gsm[];

    const int tid  = threadIdx.x;
    const int warp = tid >> 5, lane = tid & 31;
    const int wm   = warp & 3, wn = warp >> 2;
    const int grp  = lane >> 2, tg = lane & 3;
    const int n0   = blockIdx.x * 64;
    const int m0   = blockIdx.y * 128;

    const float* Ag = A + (size_t)m0 * GKK;
    const float* Bg = B + (size_t)n0 * GKK;
    const int crow = tid >> 3, ccol = (tid & 7) * 4;
    const uint32_t sbase = smem_u32(gsm);

    auto issue_copy = [&](int s, int ki) {
        const int k0 = ki * 32;
        uint32_t abase = sbase + (uint32_t)(s * STAGE_WORDS) * 4;
        uint32_t bbase = abase + AS_WORDS * 4;
#pragma unroll
        for (int it = 0; it < 4; it++)
            cp16(abase + ((crow + it * 32) * APITCH + ccol) * 4,
                 &Ag[(size_t)(crow + it * 32) * GKK + k0 + ccol]);
#pragma unroll
        for (int it = 0; it < 2; it++)
            cp16(bbase + ((crow + it * 32) * APITCH + ccol) * 4,
                 &Bg[(size_t)(crow + it * 32) * GKK + k0 + ccol]);
        CP_COMMIT();
    };

    float c[2][4][4];
#pragma unroll
    for (int mt = 0; mt < 2; mt++)
#pragma unroll
        for (int nt = 0; nt < 4; nt++)
#pragma unroll
            for (int r = 0; r < 4; r++) c[mt][nt][r] = 0.f;

    issue_copy(0, 0);
    issue_copy(1, 1);

#pragma unroll
    for (int i = 0; i < KITERS; i++) {
        if (i < KITERS - 1) { CP_WAIT(1); } else { CP_WAIT(0); }
        __syncthreads();

        const uint32_t* As = gsm + (i % 3) * STAGE_WORDS;
        const uint32_t* Bs = As + AS_WORDS;
#pragma unroll
        for (int ks = 0; ks < 4; ks++) {
            const int k8 = ks * 8;
            uint32_t a[2][4];
#pragma unroll
            for (int mt = 0; mt < 2; mt++) {
                int rbw = wm * 32 + mt * 16;
                a[mt][0] = As[(rbw + grp) * APITCH + k8 + tg];
                a[mt][1] = As[(rbw + grp + 8) * APITCH + k8 + tg];
                a[mt][2] = As[(rbw + grp) * APITCH + k8 + tg + 4];
                a[mt][3] = As[(rbw + grp + 8) * APITCH + k8 + tg + 4];
            }
#pragma unroll
            for (int nt = 0; nt < 4; nt++) {
                int nb = wn * 32 + nt * 8;
                uint32_t b0 = Bs[(nb + grp) * APITCH + k8 + tg];
                uint32_t b1 = Bs[(nb + grp) * APITCH + k8 + tg + 4];
#pragma unroll
                for (int mt = 0; mt < 2; mt++)
                    mma_tf32_16x8x8(c[mt][nt][0], c[mt][nt][1],
                                    c[mt][nt][2], c[mt][nt][3],
                                    a[mt][0], a[mt][1], a[mt][2], a[mt][3],
                                    b0, b1);
            }
        }
        if (i + 2 < KITERS) issue_copy((i + 2) % 3, i + 2);
    }

#pragma unroll
    for (int mt = 0; mt < 2; mt++) {
#pragma unroll
        for (int nt = 0; nt < 4; nt++) {
            int col = n0 + wn * 32 + nt * 8 + tg * 2;
            float b0 = bias[col], b1 = bias[col + 1];
            float s0 = (col     < scaleCols) ? scale : 1.f;
            float s1 = (col + 1 < scaleCols) ? scale : 1.f;
            int r0 = m0 + wm * 32 + mt * 16 + grp;
            float v00 = (c[mt][nt][0] + b0) * s0;
            float v01 = (c[mt][nt][1] + b1) * s1;
            float v10 = (c[mt][nt][2] + b0) * s0;
            float v11 = (c[mt][nt][3] + b1) * s1;
            if (roundOut) {
                v00 = __uint_as_float(f32_to_tf32(v00));
                v01 = __uint_as_float(f32_to_tf32(v01));
                v10 = __uint_as_float(f32_to_tf32(v10));
                v11 = __uint_as_float(f32_to_tf32(v11));
            }
            *(float2*)&C[(size_t)r0 * N + col]       = make_float2(v00, v01);
            *(float2*)&C[(size_t)(r0 + 8) * N + col] = make_float2(v10, v11);
        }
    }
}

// ---------------------------------------------------------------------------
// Table transpose: table[p][w][h] -> g_tableT[w][h][p], scaled by LOG2E.
// Per (w,h) the gather then reads from a 13KB L1-resident slice.
// ---------------------------------------------------------------------------
__global__ void table_transpose_kernel(const float* __restrict__ table)
{
    const int w = blockIdx.x, h = blockIdx.y;
    float* dst = g_tableT + (size_t)(w * NHEADS + h) * TABLE;
    for (int p = threadIdx.x; p < TABLE; p += blockDim.x)
        dst[p] = table[((size_t)p * TOW + w) * NHEADS + h] * LOG2E;
}

// ---------------------------------------------------------------------------
// Bias pre-gather into FRAGMENT-PERMUTED layout (reads L1-resident slice).
// ---------------------------------------------------------------------------
__global__ void bias_gather_kernel(const int* __restrict__ pos)
{
    const int w = blockIdx.x, h = blockIdx.y;
    const float* src = g_tableT + (size_t)(w * NHEADS + h) * TABLE;
    float* dst = g_biasg + (size_t)(h * TOW + w) * (NWIN * NWIN);
    for (int op = threadIdx.x; op < NWIN * NWIN; op += blockDim.x) {
        const int sw   = op / 2304;          // seg*3+warp
        const int rem  = op % 2304;
        const int nt   = rem / 128;
        const int rem2 = rem % 128;
        const int half = rem2 / 64;
        const int l2   = rem2 % 64;
        const int lane = l2 / 2, bb = l2 % 2;
        const int grp  = lane / 4, tg = lane % 4;
        const int i = (sw / 3) * 48 + (sw % 3) * 16 + half * 8 + grp;
        const int j = nt * 8 + tg * 2 + bb;
        dst[op] = src[pos[i * NWIN + j]];
    }
}

// ---------------------------------------------------------------------------
// Flash-style attention v10: register S, log2-domain softmax (bare EX2),
// split MMA chains. 96 thr, 3 warps, 48 rows/CTA.
// smem: KV union 23040B + Qs 6912B = 29952B
// ---------------------------------------------------------------------------
#define ATTN_THREADS 96
#define SEG_ROWS 48
#define NSEG 3
#define KP  36
#define VP  40
#define QP  36
#define KV_WORDS (NWIN * VP)                  // 5760
#define QS_OFF   KV_WORDS
#define ATTN_SMEM_B ((KV_WORDS + SEG_ROWS * QP) * 4)   // 29952

__global__ __launch_bounds__(ATTN_THREADS)
void attn_mma_kernel()
{
    extern __shared__ uint32_t smw[];
    uint32_t* KV = smw;
    uint32_t* Qs = smw + QS_OFF;

    const int w = blockIdx.x, b = blockIdx.y;
    const int h = blockIdx.z / NSEG, seg = blockIdx.z % NSEG;
    const int tid  = threadIdx.x;
    const int warp = tid >> 5, lane = tid & 31;
    const int grp  = lane >> 2, tg = lane & 3;
    const int lrb  = warp * 16;
    const int rb   = seg * SEG_ROWS + lrb;

    const size_t base = (size_t)(b * TOW + w) * NWIN * QKV_N + h * HD;
    const float* __restrict__ Qg = g_qkv + base;
    const float* __restrict__ Kg = Qg + 192;
    const float* __restrict__ Vg = Qg + 384;
    const uint32_t kvbase = smem_u32(KV);
    const uint32_t qsbase = smem_u32(Qs);

    // --- phase 1: cp.async K (pitch 36) + Q segment (pitch 36) ---
    for (int idx = tid; idx < NWIN * 8; idx += ATTN_THREADS) {
        const int i = idx >> 3, e0 = (idx & 7) * 4;
        cp16(kvbase + (i * KP + e0) * 4, &Kg[(size_t)i * QKV_N + e0]);
    }
    for (int idx = tid; idx < SEG_ROWS * 8; idx += ATTN_THREADS) {
        const int i = idx >> 3, e0 = (idx & 7) * 4;
        cp16(qsbase + (i * QP + e0) * 4,
             &Qg[(size_t)(seg * SEG_ROWS + i) * QKV_N + e0]);
    }
    CP_COMMIT();
    CP_WAIT(0);
    __syncthreads();

    // Q fragments from smem
    uint32_t aq[4][4];
#pragma unroll
    for (int kt = 0; kt < 4; kt++) {
        const int k8 = kt * 8;
        aq[kt][0] = Qs[(lrb + grp) * QP + k8 + tg];
        aq[kt][1] = Qs[(lrb + grp + 8) * QP + k8 + tg];
        aq[kt][2] = Qs[(lrb + grp) * QP + k8 + tg + 4];
        aq[kt][3] = Qs[(lrb + grp + 8) * QP + k8 + tg + 4];
    }

    // --- phase 2: S = Q K^T + bias (two independent MMA chains per n-tile) ---
    const float* bptr = g_biasg + (size_t)(h * TOW + w) * (NWIN * NWIN)
                        + (size_t)(seg * 3 + warp) * 2304;
    float sc[18][4];
#pragma unroll 3
    for (int nt = 0; nt < 18; nt++) {
        const int nb = nt * 8;
        float c0 = 0.f, c1 = 0.f, c2 = 0.f, c3 = 0.f;
        float d0 = 0.f, d1 = 0.f, d2 = 0.f, d3 = 0.f;
#pragma unroll
        for (int kt = 0; kt < 2; kt++) {
            const int k8 = kt * 8;
            uint32_t b0 = KV[(nb + grp) * KP + k8 + tg];
            uint32_t b1 = KV[(nb + grp) * KP + k8 + tg + 4];
            mma_tf32_16x8x8(c0, c1, c2, c3,
                            aq[kt][0], aq[kt][1], aq[kt][2], aq[kt][3], b0, b1);
        }
#pragma unroll
        for (int kt = 2; kt < 4; kt++) {
            const int k8 = kt * 8;
            uint32_t b0 = KV[(nb + grp) * KP + k8 + tg];
            uint32_t b1 = KV[(nb + grp) * KP + k8 + tg + 4];
            mma_tf32_16x8x8(d0, d1, d2, d3,
                            aq[kt][0], aq[kt][1], aq[kt][2], aq[kt][3], b0, b1);
        }
        float2 bv0 = *(const float2*)&bptr[nt * 128 + lane * 2];
        float2 bv1 = *(const float2*)&bptr[nt * 128 + 64 + lane * 2];
        sc[nt][0] = (c0 + d0) + bv0.x; sc[nt][1] = (c1 + d1) + bv0.y;
        sc[nt][2] = (c2 + d2) + bv1.x; sc[nt][3] = (c3 + d3) + bv1.y;
    }
    __syncthreads();   // K consumed; KV buffer free for V

    // --- phase 3: cp.async V (pitch 40) overlapped with log2-domain softmax ---
    for (int idx = tid; idx < NWIN * 8; idx += ATTN_THREADS) {
        const int i = idx >> 3, e0 = (idx & 7) * 4;
        cp16(kvbase + (i * VP + e0) * 4, &Vg[(size_t)i * QKV_N + e0]);
    }
    CP_COMMIT();

    float inv0, inv1;
    {
        float mx0 = -1e30f, mx1 = -1e30f;
#pragma unroll
        for (int nt = 0; nt < 18; nt++) {
            mx0 = fmaxf(mx0, fmaxf(sc[nt][0], sc[nt][1]));
            mx1 = fmaxf(mx1, fmaxf(sc[nt][2], sc[nt][3]));
        }
        mx0 = fmaxf(mx0, __shfl_xor_sync(0xffffffffu, mx0, 1));
        mx0 = fmaxf(mx0, __shfl_xor_sync(0xffffffffu, mx0, 2));
        mx1 = fmaxf(mx1, __shfl_xor_sync(0xffffffffu, mx1, 1));
        mx1 = fmaxf(mx1, __shfl_xor_sync(0xffffffffu, mx1, 2));
        float s0 = 0.f, s1 = 0.f;
#pragma unroll
        for (int nt = 0; nt < 18; nt++) {
            sc[nt][0] = ex2_approx(sc[nt][0] - mx0); s0 += sc[nt][0];
            sc[nt][1] = ex2_approx(sc[nt][1] - mx0); s0 += sc[nt][1];
            sc[nt][2] = ex2_approx(sc[nt][2] - mx1); s1 += sc[nt][2];
            sc[nt][3] = ex2_approx(sc[nt][3] - mx1); s1 += sc[nt][3];
        }
        s0 += __shfl_xor_sync(0xffffffffu, s0, 1);
        s0 += __shfl_xor_sync(0xffffffffu, s0, 2);
        s1 += __shfl_xor_sync(0xffffffffu, s1, 1);
        s1 += __shfl_xor_sync(0xffffffffu, s1, 2);
        inv0 = 1.f / s0; inv1 = 1.f / s1;
#pragma unroll
        for (int nt = 0; nt < 18; nt++) {
            sc[nt][0] = __uint_as_float(f32_to_tf32(sc[nt][0]));
            sc[nt][1] = __uint_as_float(f32_to_tf32(sc[nt][1]));
            sc[nt][2] = __uint_as_float(f32_to_tf32(sc[nt][2]));
            sc[nt][3] = __uint_as_float(f32_to_tf32(sc[nt][3]));
        }
    }
    CP_WAIT(0);
    __syncthreads();   // V staged

    // --- phase 4: O = P V; P C-frag -> A-frag via index shuffles ---
    float c[4][4];
#pragma unroll
    for (int nt = 0; nt < 4; nt++)
#pragma unroll
        for (int r = 0; r < 4; r++) c[nt][r] = 0.f;

    const int src0 = (lane & ~3) | (tg >> 1);
    const int src1 = src0 + 2;
    const bool odd = (tg & 1);

#pragma unroll 3
    for (int kk = 0; kk < 18; kk++) {
        const int k8 = kk * 8;
        float e0 = __shfl_sync(0xffffffffu, sc[kk][0], src0);
        float e1 = __shfl_sync(0xffffffffu, sc[kk][1], src0);
        float f0 = __shfl_sync(0xffffffffu, sc[kk][0], src1);
        float f1 = __shfl_sync(0xffffffffu, sc[kk][1], src1);
        uint32_t a0 = __float_as_uint(odd ? e1 : e0);
        uint32_t a2 = __float_as_uint(odd ? f1 : f0);
        float g0 = __shfl_sync(0xffffffffu, sc[kk][2], src0);
        float g1 = __shfl_sync(0xffffffffu, sc[kk][3], src0);
        float h0 = __shfl_sync(0xffffffffu, sc[kk][2], src1);
        float h1 = __shfl_sync(0xffffffffu, sc[kk][3], src1);
        uint32_t a1 = __float_as_uint(odd ? g1 : g0);
        uint32_t a3 = __float_as_uint(odd ? h1 : h0);
#pragma unroll
        for (int nt = 0; nt < 4; nt++) {
            uint32_t b0 = KV[(k8 + tg) * VP + nt * 8 + grp];
            uint32_t b1 = KV[(k8 + tg + 4) * VP + nt * 8 + grp];
            mma_tf32_16x8x8(c[nt][0], c[nt][1], c[nt][2], c[nt][3],
                            a0, a1, a2, a3, b0, b1);
        }
    }

    const size_t obase = (size_t)(b * TOW + w) * NWIN * DIMC + h * HD;
#pragma unroll
    for (int nt = 0; nt < 4; nt++) {
        const int col = nt * 8 + tg * 2;
        float o00 = __uint_as_float(f32_to_tf32(c[nt][0] * inv0));
        float o01 = __uint_as_float(f32_to_tf32(c[nt][1] * inv0));
        float o10 = __uint_as_float(f32_to_tf32(c[nt][2] * inv1));
        float o11 = __uint_as_float(f32_to_tf32(c[nt][3] * inv1));
        *(float2*)&g_att[obase + (size_t)(rb + grp) * DIMC + col] =
            make_float2(o00, o01);
        *(float2*)&g_att[obase + (size_t)(rb + grp + 8) * DIMC + col] =
            make_float2(o10, o11);
    }
}

// ---------------------------------------------------------------------------
extern "C" void kernel_launch(void* const* d_in, const int* in_sizes, int n_in,
                              void* d_out, int out_size)
{
    const float* x      = (const float*)d_in[0];
    const float* qkv_w  = (const float*)d_in[1];
    const float* qkv_b  = (const float*)d_in[2];
    const float* proj_w = (const float*)d_in[3];
    const float* proj_b = (const float*)d_in[4];
    const float* table  = (const float*)d_in[5];
    const int*   pos    = (const int*)d_in[6];
    float* out = (float*)d_out;

    float *qkv_s, *att_s, *xt_s, *wq_s, *wp_s;
    cudaGetSymbolAddress((void**)&qkv_s, g_qkv);
    cudaGetSymbolAddress((void**)&att_s, g_att);
    cudaGetSymbolAddress((void**)&xt_s,  g_xt);
    cudaGetSymbolAddress((void**)&wq_s,  g_wq);
    cudaGetSymbolAddress((void**)&wp_s,  g_wp);

    cudaFuncSetAttribute(gemm_tc_kernel, cudaFuncAttributeMaxDynamicSharedMemorySize,
                         GEMM_SMEM_B);
    cudaFuncSetAttribute(attn_mma_kernel, cudaFuncAttributeMaxDynamicSharedMemorySize,
                         ATTN_SMEM_B);

    // 0) pre-round inputs to tf32; transpose bias table (xLOG2E)
    {
        int n4 = MTOT * DIMC / 4;
        cvt_tf32_kernel<<<(n4 + 255) / 256, 256>>>(x, xt_s, n4);
        int w4 = QKV_N * DIMC / 4;
        cvt_tf32_kernel<<<(w4 + 255) / 256, 256>>>(qkv_w, wq_s, w4);
        int p4 = DIMC * DIMC / 4;
        cvt_tf32_kernel<<<(p4 + 255) / 256, 256>>>(proj_w, wp_s, p4);
        dim3 tg_(TOW, NHEADS);
        table_transpose_kernel<<<tg_, 256>>>(table);
    }
    // 1) bias pre-gather (fragment-permuted layout, L1-local source)
    {
        dim3 grid(TOW, NHEADS);
        bias_gather_kernel<<<grid, 256>>>(pos);
    }
    // 2) fused QKV projection (q scaled by ATT_SCALE*LOG2E for exp2 softmax)
    {
        dim3 grid(QKV_N / 64, MTOT / 128);
        gemm_tc_kernel<<<grid, 256, GEMM_SMEM_B>>>(xt_s, wq_s, qkv_b, qkv_s,
                                                   QKV_N, DIMC,
                                                   ATT_SCALE * LOG2E, 1);
    }
    // 3) windowed attention
    {
        dim3 grid(TOW, BATCH, NHEADS * NSEG);
        attn_mma_kernel<<<grid, ATTN_THREADS, ATTN_SMEM_B>>>();
    }
    // 4) output projection
    {
        dim3 grid(DIMC / 64, MTOT / 128);
        gemm_tc_kernel<<<grid, 256, GEMM_SMEM_B>>>(att_s, wp_s, proj_b, out,
                                                   DIMC, 0, 1.0f, 0);
    }
}